// round 5
// baseline (speedup 1.0000x reference)
#include <cuda_runtime.h>
#include <cuda_bf16.h>
#include <cstdint>

#define M_TOK   16384
#define L_SEQ   4096
#define D_MODEL 1024
#define DI      2048
#define DS      16
#define DH      1024

// ---------------- mma.sync GEMM tiling ----------------
// CTA 128x128, 4 warps (2x2), warp tile 64x64, BK=32, 4-stage cp.async
#define BM 128
#define BN 128
#define BK 32
#define NSTAGE 4
#define PITCH 40                      // bf16 elems per smem row (80B) -> conflict-free ldmatrix
#define STAGE_BYTES (128 * PITCH * 2) // 10240 per tile
#define SMEM_TOTAL (NSTAGE * 2 * STAGE_BYTES)  // 81920

// ---------------- scratch (device globals) ----------------
__device__ __nv_bfloat16 g_xn  [(size_t)M_TOK * D_MODEL];
__device__ __nv_bfloat16 g_gate[(size_t)M_TOK * DI];
__device__ __nv_bfloat16 g_val [(size_t)M_TOK * DI];
__device__ __nv_bfloat16 g_ca  [(size_t)M_TOK * DI];
__device__ __nv_bfloat16 g_cb  [(size_t)M_TOK * DI];
__device__ __nv_bfloat16 g_y   [(size_t)M_TOK * DI];
__device__ __nv_bfloat16 g_f   [(size_t)M_TOK * DI];

__device__ __nv_bfloat16 g_inw  [(size_t)2 * DI * D_MODEL];
__device__ __nv_bfloat16 g_fusew[(size_t)DI * DI];
__device__ __nv_bfloat16 g_outw [(size_t)D_MODEL * DI];
__device__ __nv_bfloat16 g_hbw  [(size_t)DH * DI];
__device__ __nv_bfloat16 g_pwT  [(size_t)DI * DI];
__device__ __nv_bfloat16 g_Wa   [(size_t)DH * DI];
__device__ __nv_bfloat16 g_Wb   [(size_t)DH * DI];
__device__ float         g_T    [DS * DH];
__device__ float         g_biasb[DH];

// ---------------- PTX helpers ----------------
__device__ __forceinline__ uint32_t smem_u32(const void* p) {
    uint32_t a;
    asm("{ .reg .u64 t; cvta.to.shared.u64 t, %1; cvt.u32.u64 %0, t; }" : "=r"(a) : "l"(p));
    return a;
}
__device__ __forceinline__ void cpasync16(uint32_t dst, const void* src) {
    asm volatile("cp.async.cg.shared.global [%0], [%1], 16;" :: "r"(dst), "l"(src));
}
#define CP_COMMIT() asm volatile("cp.async.commit_group;" ::: "memory")
#define CP_WAIT2()  asm volatile("cp.async.wait_group 2;" ::: "memory")
#define CP_WAIT0()  asm volatile("cp.async.wait_group 0;" ::: "memory")

__device__ __forceinline__ void ldsm4(uint32_t* r, uint32_t addr) {
    asm volatile("ldmatrix.sync.aligned.m8n8.x4.shared.b16 {%0,%1,%2,%3}, [%4];"
        : "=r"(r[0]), "=r"(r[1]), "=r"(r[2]), "=r"(r[3]) : "r"(addr));
}
__device__ __forceinline__ void mma16816(float* d, const uint32_t* a, uint32_t b0, uint32_t b1) {
    asm volatile("mma.sync.aligned.m16n8k16.row.col.f32.bf16.bf16.f32 "
        "{%0,%1,%2,%3}, {%4,%5,%6,%7}, {%8,%9}, {%0,%1,%2,%3};"
        : "+f"(d[0]), "+f"(d[1]), "+f"(d[2]), "+f"(d[3])
        : "r"(a[0]), "r"(a[1]), "r"(a[2]), "r"(a[3]), "r"(b0), "r"(b1));
}

enum { EPI_NONE = 0, EPI_SIG = 1, EPI_GATE = 2, EPI_RESID = 3 };

// C[m,n] = sum_k X[m,k]*W[n,k]; X:(M,K) bf16 row-major, W:(N,K) bf16 row-major
template<int EPI>
__global__ void __launch_bounds__(128, 2) mma_gemm_k(
    const __nv_bfloat16* __restrict__ X, const __nv_bfloat16* __restrict__ W,
    const float* __restrict__ bias, void* __restrict__ outp, int out_stride,
    const __nv_bfloat16* __restrict__ gate, const float* __restrict__ resid,
    int K)
{
    extern __shared__ char smem[];
    uint32_t sA = smem_u32(smem);
    uint32_t sB = sA + NSTAGE * STAGE_BYTES;
    int tid = threadIdx.x, warp = tid >> 5, lane = tid & 31;
    int wm = warp >> 1, wn = warp & 1;           // 2 x 2 warp grid, warp tile 64x64
    int bm = blockIdx.y * BM, bn = blockIdx.x * BN;
    int NC = K / BK;

    float acc[4][8][4];
    #pragma unroll
    for (int mi = 0; mi < 4; mi++)
        #pragma unroll
        for (int nj = 0; nj < 8; nj++)
            #pragma unroll
            for (int e = 0; e < 4; e++) acc[mi][nj][e] = 0.f;

    // stage: A 128x32 + B 128x32, 16B chunks; 128 threads x 4 chunks per tile
    auto stage_load = [&](int st, int c) {
        uint32_t a = sA + st * STAGE_BYTES;
        uint32_t b = sB + st * STAGE_BYTES;
        int k0 = c * BK;
        #pragma unroll
        for (int it = 0; it < 4; it++) {
            int id = tid + it * 128;
            int r = id >> 2, s = id & 3;
            uint32_t off = (uint32_t)(r * PITCH + s * 8) * 2;
            cpasync16(a + off, X + (size_t)(bm + r) * K + k0 + s * 8);
            cpasync16(b + off, W + (size_t)(bn + r) * K + k0 + s * 8);
        }
    };

    #pragma unroll
    for (int c = 0; c < NSTAGE - 1; c++) {
        stage_load(c, c);
        CP_COMMIT();
    }

    // ldmatrix address components (lane-invariant parts hoisted)
    int lrow = lane & 15;
    int lcol8 = (lane >> 4) * 8;

    for (int c = 0; c < NC; c++) {
        int st = c & (NSTAGE - 1);
        CP_WAIT2();
        __syncthreads();
        if (c + NSTAGE - 1 < NC) stage_load((c + NSTAGE - 1) & (NSTAGE - 1), c + NSTAGE - 1);
        CP_COMMIT();

        uint32_t aBase = sA + st * STAGE_BYTES;
        uint32_t bBase = sB + st * STAGE_BYTES;
        #pragma unroll
        for (int kk = 0; kk < 2; kk++) {
            uint32_t af[4][4], bf[4][4];
            #pragma unroll
            for (int mi = 0; mi < 4; mi++) {
                int row = wm * 64 + mi * 16 + lrow;
                ldsm4(af[mi], aBase + (uint32_t)(row * PITCH + kk * 16 + lcol8) * 2);
            }
            #pragma unroll
            for (int ni = 0; ni < 4; ni++) {
                int row = wn * 64 + ni * 16 + lrow;
                ldsm4(bf[ni], bBase + (uint32_t)(row * PITCH + kk * 16 + lcol8) * 2);
            }
            // ldsm4 on B: regs {0,2} = first n8 (k0-7,k8-15), {1,3} = second n8
            #pragma unroll
            for (int mi = 0; mi < 4; mi++)
                #pragma unroll
                for (int ni = 0; ni < 4; ni++) {
                    mma16816(acc[mi][2 * ni + 0], af[mi], bf[ni][0], bf[ni][2]);
                    mma16816(acc[mi][2 * ni + 1], af[mi], bf[ni][1], bf[ni][3]);
                }
        }
    }
    CP_WAIT0();

    // -------- register epilogue --------
    #pragma unroll
    for (int mi = 0; mi < 4; mi++) {
        #pragma unroll
        for (int nj = 0; nj < 8; nj++) {
            int gn = bn + wn * 64 + nj * 8 + (lane & 3) * 2;
            float b0 = 0.f, b1 = 0.f;
            if (bias) { b0 = bias[gn]; b1 = bias[gn + 1]; }
            #pragma unroll
            for (int h = 0; h < 2; h++) {
                int gm = bm + wm * 64 + mi * 16 + (lane >> 2) + h * 8;
                float v0 = acc[mi][nj][h * 2 + 0] + b0;
                float v1 = acc[mi][nj][h * 2 + 1] + b1;
                if (EPI == EPI_SIG) {
                    v0 = 1.f / (1.f + __expf(-v0));
                    v1 = 1.f / (1.f + __expf(-v1));
                }
                if (EPI == EPI_GATE) {
                    __nv_bfloat162 g2 = *(const __nv_bfloat162*)(gate + (size_t)gm * DI + gn);
                    v0 *= __bfloat162float(g2.x);
                    v1 *= __bfloat162float(g2.y);
                }
                if (EPI == EPI_RESID) {
                    const float* rp = resid + (size_t)gm * out_stride + gn;
                    float* op = (float*)outp + (size_t)gm * out_stride + gn;
                    float2 r2 = *(const float2*)rp;
                    float2 o2; o2.x = v0 + r2.x; o2.y = v1 + r2.y;
                    *(float2*)op = o2;
                } else {
                    __nv_bfloat16* op = (__nv_bfloat16*)outp + (size_t)gm * out_stride + gn;
                    *(__nv_bfloat162*)op = __floats2bfloat162_rn(v0, v1);
                }
            }
        }
    }
}

// ---------------- small kernels ----------------
__global__ void f2bf_k(const float* __restrict__ s, __nv_bfloat16* __restrict__ d, int n) {
    int i = blockIdx.x * 256 + threadIdx.x;
    if (i < n) d[i] = __float2bfloat16(s[i]);
}

__global__ void rmsnorm_k(const float* __restrict__ x, const float* __restrict__ w) {
    int row = blockIdx.x;
    int tid = threadIdx.x;
    const float* xr = x + (size_t)row * D_MODEL;
    float s = 0.f;
    for (int i = tid; i < D_MODEL; i += 256) { float v = xr[i]; s += v * v; }
    __shared__ float red[256];
    red[tid] = s; __syncthreads();
    for (int o = 128; o > 0; o >>= 1) {
        if (tid < o) red[tid] += red[tid + o];
        __syncthreads();
    }
    float scale = rsqrtf(red[0] / (float)D_MODEL + 1e-6f);
    for (int i = tid; i < D_MODEL; i += 256)
        g_xn[(size_t)row * D_MODEL + i] = __float2bfloat16(xr[i] * w[i] * scale);
}

// 32x32 tiled transpose: g_pwT[c][o] = pw_w[o][c], fp32 -> bf16
__global__ void transpose_pw_k(const float* __restrict__ src) {
    __shared__ float t[32][33];
    int bx = blockIdx.x * 32, by = blockIdx.y * 32;
    int tx = threadIdx.x, ty = threadIdx.y;
    #pragma unroll
    for (int i = 0; i < 32; i += 8)
        t[ty + i][tx] = src[(size_t)(by + ty + i) * DI + bx + tx];
    __syncthreads();
    #pragma unroll
    for (int i = 0; i < 32; i += 8)
        g_pwT[(size_t)(bx + ty + i) * DI + by + tx] = __float2bfloat16(t[tx][ty + i]);
}

// fused depthwise convs: a (4-tap, pad 1,2) and b = silu(9-tap, pad 4,4)
#define CL 128
#define CD 64
__global__ void __launch_bounds__(256) conv_fused_k(
    const float* __restrict__ ka, const float* __restrict__ ba,
    const float* __restrict__ ks, const float* __restrict__ bs)
{
    __shared__ __nv_bfloat16 sv[CL + 8][CD];
    int d0 = blockIdx.x * CD;
    int l0 = blockIdx.y * CL;
    int b  = blockIdx.z;
    const __nv_bfloat16* vb = g_val + (size_t)b * L_SEQ * DI;
    int tid = threadIdx.x;
    for (int i = tid; i < (CL + 8) * 8; i += 256) {
        int r = i >> 3, s = i & 7;
        int l = l0 - 4 + r;
        uint4 v = make_uint4(0, 0, 0, 0);
        if (l >= 0 && l < L_SEQ)
            v = *(const uint4*)(vb + (size_t)l * DI + d0 + s * 8);
        *(uint4*)(&sv[r][s * 8]) = v;
    }
    __syncthreads();
    int d = tid & (CD - 1);
    int lw = tid >> 6;
    float wa[4], w9[9];
    #pragma unroll
    for (int j = 0; j < 4; j++) wa[j] = ka[(d0 + d) * 4 + j];
    #pragma unroll
    for (int j = 0; j < 9; j++) w9[j] = ks[(d0 + d) * 9 + j];
    float bav = ba[d0 + d], bsv = bs[d0 + d];
    for (int li = 0; li < CL / 4; li++) {
        int l = lw * (CL / 4) + li;
        float aa = bav, ab = bsv;
        #pragma unroll
        for (int j = 0; j < 4; j++) aa += __bfloat162float(sv[l + 3 + j][d]) * wa[j];
        #pragma unroll
        for (int j = 0; j < 9; j++) ab += __bfloat162float(sv[l + j][d]) * w9[j];
        size_t o = ((size_t)b * L_SEQ + l0 + l) * DI + d0 + d;
        g_ca[o] = __float2bfloat16(aa);
        float sg = 1.f / (1.f + __expf(-ab));
        g_cb[o] = __float2bfloat16(ab * sg);
    }
}

// T[s][n] = sum_d Bm[s,d] * ha_w[n,d]
__global__ void compute_T_k(const float* __restrict__ Bm, const float* __restrict__ haw) {
    int n = blockIdx.x;
    int tid = threadIdx.x;
    float acc[DS];
    #pragma unroll
    for (int s = 0; s < DS; s++) acc[s] = 0.f;
    for (int d = tid; d < DI; d += 128) {
        float h = haw[(size_t)n * DI + d];
        #pragma unroll
        for (int s = 0; s < DS; s++) acc[s] += h * Bm[s * DI + d];
    }
    __shared__ float red[DS * 128];
    #pragma unroll
    for (int s = 0; s < DS; s++) red[s * 128 + tid] = acc[s];
    __syncthreads();
    if (tid < DS) {
        float t = 0.f;
        for (int i = 0; i < 128; i++) t += red[tid * 128 + i];
        g_T[tid * DH + n] = t;
    }
}

// Wa[n][k] = sum_s A[k,s] * T[s][n]
__global__ void compute_Wa_k(const float* __restrict__ A) {
    int idx = blockIdx.x * 256 + threadIdx.x;
    int k = idx & (DI - 1);
    int n = idx >> 11;
    float acc = 0.f;
    #pragma unroll
    for (int s = 0; s < DS; s++) acc += A[k * DS + s] * g_T[s * DH + n];
    g_Wa[(size_t)n * DI + k] = __float2bfloat16(acc);
}

// bias_b[n] = hb_b[n] + sum_d hb_w[n,d]*pw_b[d]
__global__ void bias_b_k(const float* __restrict__ hbw, const float* __restrict__ pwb,
                         const float* __restrict__ hbb) {
    int n = blockIdx.x;
    int tid = threadIdx.x;
    float a = 0.f;
    for (int d = tid; d < DI; d += 256) a += hbw[(size_t)n * DI + d] * pwb[d];
    __shared__ float red[256];
    red[tid] = a; __syncthreads();
    for (int o = 128; o > 0; o >>= 1) {
        if (tid < o) red[tid] += red[tid + o];
        __syncthreads();
    }
    if (tid == 0) g_biasb[n] = red[0] + hbb[n];
}

// ---------------- launch ----------------
static void* sym_addr(const void* s) {
    void* p = nullptr;
    cudaGetSymbolAddress(&p, s);
    return p;
}

extern "C" void kernel_launch(void* const* d_in, const int* in_sizes, int n_in,
                              void* d_out, int out_size) {
    const float* x      = (const float*)d_in[0];
    const float* norm_w = (const float*)d_in[1];
    const float* in_w   = (const float*)d_in[2];
    const float* in_b   = (const float*)d_in[3];
    const float* dwa_k  = (const float*)d_in[4];
    const float* dwa_b  = (const float*)d_in[5];
    const float* A      = (const float*)d_in[6];
    const float* Bm     = (const float*)d_in[7];
    const float* sym_k  = (const float*)d_in[8];
    const float* sym_b  = (const float*)d_in[9];
    const float* pw_w   = (const float*)d_in[10];
    const float* pw_b   = (const float*)d_in[11];
    const float* ha_w   = (const float*)d_in[12];
    const float* ha_b   = (const float*)d_in[13];
    const float* hb_w   = (const float*)d_in[14];
    const float* hb_b   = (const float*)d_in[15];
    const float* fuse_w = (const float*)d_in[16];
    const float* fuse_b = (const float*)d_in[17];
    const float* out_w  = (const float*)d_in[18];
    const float* out_b  = (const float*)d_in[19];

    __nv_bfloat16* p_xn    = (__nv_bfloat16*)sym_addr(g_xn);
    __nv_bfloat16* p_gate  = (__nv_bfloat16*)sym_addr(g_gate);
    __nv_bfloat16* p_ca    = (__nv_bfloat16*)sym_addr(g_ca);
    __nv_bfloat16* p_cb    = (__nv_bfloat16*)sym_addr(g_cb);
    __nv_bfloat16* p_val   = (__nv_bfloat16*)sym_addr(g_val);
    __nv_bfloat16* p_y     = (__nv_bfloat16*)sym_addr(g_y);
    __nv_bfloat16* p_f     = (__nv_bfloat16*)sym_addr(g_f);
    __nv_bfloat16* p_inw   = (__nv_bfloat16*)sym_addr(g_inw);
    __nv_bfloat16* p_fusew = (__nv_bfloat16*)sym_addr(g_fusew);
    __nv_bfloat16* p_outw  = (__nv_bfloat16*)sym_addr(g_outw);
    __nv_bfloat16* p_hbw   = (__nv_bfloat16*)sym_addr(g_hbw);
    __nv_bfloat16* p_pwT   = (__nv_bfloat16*)sym_addr(g_pwT);
    __nv_bfloat16* p_Wa    = (__nv_bfloat16*)sym_addr(g_Wa);
    __nv_bfloat16* p_Wb    = (__nv_bfloat16*)sym_addr(g_Wb);
    float*         p_biasb = (float*)sym_addr(g_biasb);

    cudaFuncSetAttribute(mma_gemm_k<EPI_NONE>,  cudaFuncAttributeMaxDynamicSharedMemorySize, SMEM_TOTAL);
    cudaFuncSetAttribute(mma_gemm_k<EPI_SIG>,   cudaFuncAttributeMaxDynamicSharedMemorySize, SMEM_TOTAL);
    cudaFuncSetAttribute(mma_gemm_k<EPI_GATE>,  cudaFuncAttributeMaxDynamicSharedMemorySize, SMEM_TOTAL);
    cudaFuncSetAttribute(mma_gemm_k<EPI_RESID>, cudaFuncAttributeMaxDynamicSharedMemorySize, SMEM_TOTAL);

    auto cgrid = [](int n) { return (n + 255) / 256; };

    // launches 1..4 (1-based), so launch #5 is the gate GEMM (ncu -s 5 -c 1 target)
    rmsnorm_k<<<M_TOK, 256>>>(x, norm_w);
    f2bf_k<<<cgrid(2 * DI * D_MODEL), 256>>>(in_w,   p_inw,   2 * DI * D_MODEL);
    f2bf_k<<<cgrid(DI * DI), 256>>>(fuse_w, p_fusew, DI * DI);
    f2bf_k<<<cgrid(D_MODEL * DI), 256>>>(out_w,  p_outw,  D_MODEL * DI);

    // in_proj: gate (sigmoid) and val
    dim3 gdIn(DI / BN, M_TOK / BM);
    mma_gemm_k<EPI_SIG><<<gdIn, 128, SMEM_TOTAL>>>(p_xn, p_inw, in_b, p_gate, DI,
                                                   nullptr, nullptr, D_MODEL);
    mma_gemm_k<EPI_NONE><<<gdIn, 128, SMEM_TOTAL>>>(p_xn, p_inw + (size_t)DI * D_MODEL,
                                                    in_b + DI, p_val, DI,
                                                    nullptr, nullptr, D_MODEL);

    f2bf_k<<<cgrid(DH * DI), 256>>>(hb_w, p_hbw, DH * DI);
    transpose_pw_k<<<dim3(DI / 32, DI / 32), dim3(32, 8)>>>(pw_w);

    conv_fused_k<<<dim3(DI / CD, L_SEQ / CL, 4), 256>>>(dwa_k, dwa_b, sym_k, sym_b);

    // folded weight precomputes
    compute_T_k<<<DH, 128>>>(Bm, ha_w);
    compute_Wa_k<<<(DH * DI) / 256, 256>>>(A);
    mma_gemm_k<EPI_NONE><<<dim3(DI / BN, DH / BM), 128, SMEM_TOTAL>>>(
        p_hbw, p_pwT, nullptr, p_Wb, DI, nullptr, nullptr, DI);
    bias_b_k<<<DH, 256>>>(hb_w, pw_b, hb_b);

    // half projections -> concat into g_y
    dim3 gdH(DH / BN, M_TOK / BM);
    mma_gemm_k<EPI_NONE><<<gdH, 128, SMEM_TOTAL>>>(p_ca, p_Wa, ha_b, p_y, DI,
                                                   nullptr, nullptr, DI);
    mma_gemm_k<EPI_NONE><<<gdH, 128, SMEM_TOTAL>>>(p_cb, p_Wb, p_biasb, p_y + DH, DI,
                                                   nullptr, nullptr, DI);

    // fuse (+ gate multiply)
    mma_gemm_k<EPI_GATE><<<dim3(DI / BN, M_TOK / BM), 128, SMEM_TOTAL>>>(
        p_y, p_fusew, fuse_b, p_f, DI, p_gate, nullptr, DI);

    // out projection (+ residual), fp32 output
    mma_gemm_k<EPI_RESID><<<dim3(D_MODEL / BN, M_TOK / BM), 128, SMEM_TOTAL>>>(
        p_f, p_outw, out_b, d_out, D_MODEL, nullptr, x, DI);
}

// round 7
// speedup vs baseline: 1.0256x; 1.0256x over previous
#include <cuda_runtime.h>
#include <cuda_bf16.h>
#include <cstdint>

#define M_TOK   16384
#define L_SEQ   4096
#define D_MODEL 1024
#define DI      2048
#define DS      16
#define DH      1024

// ---------------- mma.sync GEMM tiling ----------------
// CTA 128x128, 8 warps (2x4), warp tile 64x32, BK=32, 4-stage cp.async
#define BM 128
#define BN 128
#define BK 32
#define NSTAGE 4
#define PITCH 40                      // bf16 elems per smem row (80B) -> conflict-free ldmatrix
#define STAGE_BYTES (128 * PITCH * 2) // 10240 per tile
#define SMEM_TOTAL (NSTAGE * 2 * STAGE_BYTES)  // 81920

// ---------------- scratch (device globals) ----------------
__device__ __nv_bfloat16 g_xn  [(size_t)M_TOK * D_MODEL];
__device__ __nv_bfloat16 g_gate[(size_t)M_TOK * DI];
__device__ __nv_bfloat16 g_val [(size_t)M_TOK * DI];
__device__ __nv_bfloat16 g_ca  [(size_t)M_TOK * DI];
__device__ __nv_bfloat16 g_cb  [(size_t)M_TOK * DI];
__device__ __nv_bfloat16 g_y   [(size_t)M_TOK * DI];
__device__ __nv_bfloat16 g_f   [(size_t)M_TOK * DI];

__device__ __nv_bfloat16 g_inw  [(size_t)2 * DI * D_MODEL];
__device__ __nv_bfloat16 g_fusew[(size_t)DI * DI];
__device__ __nv_bfloat16 g_outw [(size_t)D_MODEL * DI];
__device__ __nv_bfloat16 g_hbw  [(size_t)DH * DI];
__device__ __nv_bfloat16 g_pwT  [(size_t)DI * DI];
__device__ __nv_bfloat16 g_Wa   [(size_t)DH * DI];
__device__ __nv_bfloat16 g_Wb   [(size_t)DH * DI];
__device__ float         g_T    [DS * DH];
__device__ float         g_biasb[DH];

// ---------------- PTX helpers ----------------
__device__ __forceinline__ uint32_t smem_u32(const void* p) {
    uint32_t a;
    asm("{ .reg .u64 t; cvta.to.shared.u64 t, %1; cvt.u32.u64 %0, t; }" : "=r"(a) : "l"(p));
    return a;
}
__device__ __forceinline__ void cpasync16(uint32_t dst, const void* src) {
    asm volatile("cp.async.cg.shared.global [%0], [%1], 16;" :: "r"(dst), "l"(src));
}
#define CP_COMMIT() asm volatile("cp.async.commit_group;" ::: "memory")
#define CP_WAIT2()  asm volatile("cp.async.wait_group 2;" ::: "memory")
#define CP_WAIT0()  asm volatile("cp.async.wait_group 0;" ::: "memory")

__device__ __forceinline__ void ldsm4(uint32_t* r, uint32_t addr) {
    asm volatile("ldmatrix.sync.aligned.m8n8.x4.shared.b16 {%0,%1,%2,%3}, [%4];"
        : "=r"(r[0]), "=r"(r[1]), "=r"(r[2]), "=r"(r[3]) : "r"(addr));
}
__device__ __forceinline__ void mma16816(float* d, const uint32_t* a, uint32_t b0, uint32_t b1) {
    asm volatile("mma.sync.aligned.m16n8k16.row.col.f32.bf16.bf16.f32 "
        "{%0,%1,%2,%3}, {%4,%5,%6,%7}, {%8,%9}, {%0,%1,%2,%3};"
        : "+f"(d[0]), "+f"(d[1]), "+f"(d[2]), "+f"(d[3])
        : "r"(a[0]), "r"(a[1]), "r"(a[2]), "r"(a[3]), "r"(b0), "r"(b1));
}

enum { EPI_NONE = 0, EPI_SIG = 1, EPI_GATE = 2, EPI_RESID = 3 };

// C[m,n] = sum_k X[m,k]*W[n,k]; X:(M,K) bf16 row-major, W:(N,K) bf16 row-major
template<int EPI>
__global__ void __launch_bounds__(256, 2) mma_gemm_k(
    const __nv_bfloat16* __restrict__ X, const __nv_bfloat16* __restrict__ W,
    const float* __restrict__ bias, void* __restrict__ outp, int out_stride,
    const __nv_bfloat16* __restrict__ gate, const float* __restrict__ resid,
    int K)
{
    extern __shared__ char smem[];
    uint32_t sA = smem_u32(smem);
    uint32_t sB = sA + NSTAGE * STAGE_BYTES;
    int tid = threadIdx.x, warp = tid >> 5, lane = tid & 31;
    int wm = warp >> 2, wn = warp & 3;           // 2 x 4 warp grid, warp tile 64x32
    int bm = blockIdx.y * BM, bn = blockIdx.x * BN;
    int NC = K / BK;

    float acc[4][4][4];
    #pragma unroll
    for (int mi = 0; mi < 4; mi++)
        #pragma unroll
        for (int ni = 0; ni < 4; ni++)
            #pragma unroll
            for (int e = 0; e < 4; e++) acc[mi][ni][e] = 0.f;

    // stage: A 128x32 + B 128x32, 16B chunks; 256 threads x 2 chunks per tile
    auto stage_load = [&](int st, int c) {
        uint32_t a = sA + st * STAGE_BYTES;
        uint32_t b = sB + st * STAGE_BYTES;
        int k0 = c * BK;
        #pragma unroll
        for (int it = 0; it < 2; it++) {
            int id = tid + it * 256;
            int r = id >> 2, s = id & 3;
            uint32_t off = (uint32_t)(r * PITCH + s * 8) * 2;
            cpasync16(a + off, X + (size_t)(bm + r) * K + k0 + s * 8);
            cpasync16(b + off, W + (size_t)(bn + r) * K + k0 + s * 8);
        }
    };

    #pragma unroll
    for (int c = 0; c < NSTAGE - 1; c++) {
        stage_load(c, c);
        CP_COMMIT();
    }

    // ldmatrix lane addressing (x4 form: 16 rows x 16B)
    int lrow = lane & 15;
    int lcol8 = (lane >> 4) * 8;
    // per-warp row bases in bytes
    uint32_t aRow = (uint32_t)((wm * 64 + lrow) * PITCH + lcol8) * 2;
    uint32_t bRow = (uint32_t)((wn * 32 + lrow) * PITCH + lcol8) * 2;

    for (int c = 0; c < NC; c++) {
        int st = c & (NSTAGE - 1);
        CP_WAIT2();
        __syncthreads();
        if (c + NSTAGE - 1 < NC) stage_load((c + NSTAGE - 1) & (NSTAGE - 1), c + NSTAGE - 1);
        CP_COMMIT();

        uint32_t aBase = sA + st * STAGE_BYTES + aRow;
        uint32_t bBase = sB + st * STAGE_BYTES + bRow;

        // prefetch ALL fragments for this chunk (both k16 halves), then run 32 HMMA
        uint32_t af[2][4][4];   // [kk][mi][4]
        uint32_t bf[2][2][4];   // [kk][bi][4]: bi covers 16 rows = 2 n8 groups
        #pragma unroll
        for (int kk = 0; kk < 2; kk++) {
            #pragma unroll
            for (int mi = 0; mi < 4; mi++)
                ldsm4(af[kk][mi], aBase + (uint32_t)(mi * 16 * PITCH + kk * 16) * 2);
            #pragma unroll
            for (int bi = 0; bi < 2; bi++)
                ldsm4(bf[kk][bi], bBase + (uint32_t)(bi * 16 * PITCH + kk * 16) * 2);
        }
        // ldsm4 on B rows: regs {0,2} = n8 group 0 (k0-7, k8-15), {1,3} = n8 group 1
        #pragma unroll
        for (int kk = 0; kk < 2; kk++)
            #pragma unroll
            for (int mi = 0; mi < 4; mi++)
                #pragma unroll
                for (int ni = 0; ni < 4; ni++) {
                    int bi = ni >> 1, sel = ni & 1;
                    mma16816(acc[mi][ni], af[kk][mi], bf[kk][bi][sel], bf[kk][bi][sel + 2]);
                }
    }
    CP_WAIT0();

    // -------- register epilogue --------
    #pragma unroll
    for (int mi = 0; mi < 4; mi++) {
        #pragma unroll
        for (int ni = 0; ni < 4; ni++) {
            int gn = bn + wn * 32 + ni * 8 + (lane & 3) * 2;
            float b0 = 0.f, b1 = 0.f;
            if (bias) { b0 = bias[gn]; b1 = bias[gn + 1]; }
            #pragma unroll
            for (int h = 0; h < 2; h++) {
                int gm = bm + wm * 64 + mi * 16 + (lane >> 2) + h * 8;
                float v0 = acc[mi][ni][h * 2 + 0] + b0;
                float v1 = acc[mi][ni][h * 2 + 1] + b1;
                if (EPI == EPI_SIG) {
                    v0 = 1.f / (1.f + __expf(-v0));
                    v1 = 1.f / (1.f + __expf(-v1));
                }
                if (EPI == EPI_GATE) {
                    __nv_bfloat162 g2 = *(const __nv_bfloat162*)(gate + (size_t)gm * DI + gn);
                    v0 *= __bfloat162float(g2.x);
                    v1 *= __bfloat162float(g2.y);
                }
                if (EPI == EPI_RESID) {
                    const float* rp = resid + (size_t)gm * out_stride + gn;
                    float* op = (float*)outp + (size_t)gm * out_stride + gn;
                    float2 r2 = *(const float2*)rp;
                    float2 o2; o2.x = v0 + r2.x; o2.y = v1 + r2.y;
                    *(float2*)op = o2;
                } else {
                    __nv_bfloat16* op = (__nv_bfloat16*)outp + (size_t)gm * out_stride + gn;
                    *(__nv_bfloat162*)op = __floats2bfloat162_rn(v0, v1);
                }
            }
        }
    }
}

// ---------------- small kernels ----------------
__global__ void f2bf_k(const float* __restrict__ s, __nv_bfloat16* __restrict__ d, int n) {
    int i = blockIdx.x * 256 + threadIdx.x;
    if (i < n) d[i] = __float2bfloat16(s[i]);
}

__global__ void rmsnorm_k(const float* __restrict__ x, const float* __restrict__ w) {
    int row = blockIdx.x;
    int tid = threadIdx.x;
    const float* xr = x + (size_t)row * D_MODEL;
    float s = 0.f;
    for (int i = tid; i < D_MODEL; i += 256) { float v = xr[i]; s += v * v; }
    __shared__ float red[256];
    red[tid] = s; __syncthreads();
    for (int o = 128; o > 0; o >>= 1) {
        if (tid < o) red[tid] += red[tid + o];
        __syncthreads();
    }
    float scale = rsqrtf(red[0] / (float)D_MODEL + 1e-6f);
    for (int i = tid; i < D_MODEL; i += 256)
        g_xn[(size_t)row * D_MODEL + i] = __float2bfloat16(xr[i] * w[i] * scale);
}

// 32x32 tiled transpose: g_pwT[c][o] = pw_w[o][c], fp32 -> bf16
__global__ void transpose_pw_k(const float* __restrict__ src) {
    __shared__ float t[32][33];
    int bx = blockIdx.x * 32, by = blockIdx.y * 32;
    int tx = threadIdx.x, ty = threadIdx.y;
    #pragma unroll
    for (int i = 0; i < 32; i += 8)
        t[ty + i][tx] = src[(size_t)(by + ty + i) * DI + bx + tx];
    __syncthreads();
    #pragma unroll
    for (int i = 0; i < 32; i += 8)
        g_pwT[(size_t)(bx + ty + i) * DI + by + tx] = __float2bfloat16(t[tx][ty + i]);
}

// fused depthwise convs: a (4-tap, pad 1,2) and b = silu(9-tap, pad 4,4)
#define CL 128
#define CD 64
__global__ void __launch_bounds__(256) conv_fused_k(
    const float* __restrict__ ka, const float* __restrict__ ba,
    const float* __restrict__ ks, const float* __restrict__ bs)
{
    __shared__ __nv_bfloat16 sv[CL + 8][CD];
    int d0 = blockIdx.x * CD;
    int l0 = blockIdx.y * CL;
    int b  = blockIdx.z;
    const __nv_bfloat16* vb = g_val + (size_t)b * L_SEQ * DI;
    int tid = threadIdx.x;
    for (int i = tid; i < (CL + 8) * 8; i += 256) {
        int r = i >> 3, s = i & 7;
        int l = l0 - 4 + r;
        uint4 v = make_uint4(0, 0, 0, 0);
        if (l >= 0 && l < L_SEQ)
            v = *(const uint4*)(vb + (size_t)l * DI + d0 + s * 8);
        *(uint4*)(&sv[r][s * 8]) = v;
    }
    __syncthreads();
    int d = tid & (CD - 1);
    int lw = tid >> 6;
    float wa[4], w9[9];
    #pragma unroll
    for (int j = 0; j < 4; j++) wa[j] = ka[(d0 + d) * 4 + j];
    #pragma unroll
    for (int j = 0; j < 9; j++) w9[j] = ks[(d0 + d) * 9 + j];
    float bav = ba[d0 + d], bsv = bs[d0 + d];
    for (int li = 0; li < CL / 4; li++) {
        int l = lw * (CL / 4) + li;
        float aa = bav, ab = bsv;
        #pragma unroll
        for (int j = 0; j < 4; j++) aa += __bfloat162float(sv[l + 3 + j][d]) * wa[j];
        #pragma unroll
        for (int j = 0; j < 9; j++) ab += __bfloat162float(sv[l + j][d]) * w9[j];
        size_t o = ((size_t)b * L_SEQ + l0 + l) * DI + d0 + d;
        g_ca[o] = __float2bfloat16(aa);
        float sg = 1.f / (1.f + __expf(-ab));
        g_cb[o] = __float2bfloat16(ab * sg);
    }
}

// T[s][n] = sum_d Bm[s,d] * ha_w[n,d]
__global__ void compute_T_k(const float* __restrict__ Bm, const float* __restrict__ haw) {
    int n = blockIdx.x;
    int tid = threadIdx.x;
    float acc[DS];
    #pragma unroll
    for (int s = 0; s < DS; s++) acc[s] = 0.f;
    for (int d = tid; d < DI; d += 128) {
        float h = haw[(size_t)n * DI + d];
        #pragma unroll
        for (int s = 0; s < DS; s++) acc[s] += h * Bm[s * DI + d];
    }
    __shared__ float red[DS * 128];
    #pragma unroll
    for (int s = 0; s < DS; s++) red[s * 128 + tid] = acc[s];
    __syncthreads();
    if (tid < DS) {
        float t = 0.f;
        for (int i = 0; i < 128; i++) t += red[tid * 128 + i];
        g_T[tid * DH + n] = t;
    }
}

// Wa[n][k] = sum_s A[k,s] * T[s][n]
__global__ void compute_Wa_k(const float* __restrict__ A) {
    int idx = blockIdx.x * 256 + threadIdx.x;
    int k = idx & (DI - 1);
    int n = idx >> 11;
    float acc = 0.f;
    #pragma unroll
    for (int s = 0; s < DS; s++) acc += A[k * DS + s] * g_T[s * DH + n];
    g_Wa[(size_t)n * DI + k] = __float2bfloat16(acc);
}

// bias_b[n] = hb_b[n] + sum_d hb_w[n,d]*pw_b[d]
__global__ void bias_b_k(const float* __restrict__ hbw, const float* __restrict__ pwb,
                         const float* __restrict__ hbb) {
    int n = blockIdx.x;
    int tid = threadIdx.x;
    float a = 0.f;
    for (int d = tid; d < DI; d += 256) a += hbw[(size_t)n * DI + d] * pwb[d];
    __shared__ float red[256];
    red[tid] = a; __syncthreads();
    for (int o = 128; o > 0; o >>= 1) {
        if (tid < o) red[tid] += red[tid + o];
        __syncthreads();
    }
    if (tid == 0) g_biasb[n] = red[0] + hbb[n];
}

// ---------------- launch ----------------
static void* sym_addr(const void* s) {
    void* p = nullptr;
    cudaGetSymbolAddress(&p, s);
    return p;
}

extern "C" void kernel_launch(void* const* d_in, const int* in_sizes, int n_in,
                              void* d_out, int out_size) {
    const float* x      = (const float*)d_in[0];
    const float* norm_w = (const float*)d_in[1];
    const float* in_w   = (const float*)d_in[2];
    const float* in_b   = (const float*)d_in[3];
    const float* dwa_k  = (const float*)d_in[4];
    const float* dwa_b  = (const float*)d_in[5];
    const float* A      = (const float*)d_in[6];
    const float* Bm     = (const float*)d_in[7];
    const float* sym_k  = (const float*)d_in[8];
    const float* sym_b  = (const float*)d_in[9];
    const float* pw_w   = (const float*)d_in[10];
    const float* pw_b   = (const float*)d_in[11];
    const float* ha_w   = (const float*)d_in[12];
    const float* ha_b   = (const float*)d_in[13];
    const float* hb_w   = (const float*)d_in[14];
    const float* hb_b   = (const float*)d_in[15];
    const float* fuse_w = (const float*)d_in[16];
    const float* fuse_b = (const float*)d_in[17];
    const float* out_w  = (const float*)d_in[18];
    const float* out_b  = (const float*)d_in[19];

    __nv_bfloat16* p_xn    = (__nv_bfloat16*)sym_addr(g_xn);
    __nv_bfloat16* p_gate  = (__nv_bfloat16*)sym_addr(g_gate);
    __nv_bfloat16* p_ca    = (__nv_bfloat16*)sym_addr(g_ca);
    __nv_bfloat16* p_cb    = (__nv_bfloat16*)sym_addr(g_cb);
    __nv_bfloat16* p_val   = (__nv_bfloat16*)sym_addr(g_val);
    __nv_bfloat16* p_y     = (__nv_bfloat16*)sym_addr(g_y);
    __nv_bfloat16* p_f     = (__nv_bfloat16*)sym_addr(g_f);
    __nv_bfloat16* p_inw   = (__nv_bfloat16*)sym_addr(g_inw);
    __nv_bfloat16* p_fusew = (__nv_bfloat16*)sym_addr(g_fusew);
    __nv_bfloat16* p_outw  = (__nv_bfloat16*)sym_addr(g_outw);
    __nv_bfloat16* p_hbw   = (__nv_bfloat16*)sym_addr(g_hbw);
    __nv_bfloat16* p_pwT   = (__nv_bfloat16*)sym_addr(g_pwT);
    __nv_bfloat16* p_Wa    = (__nv_bfloat16*)sym_addr(g_Wa);
    __nv_bfloat16* p_Wb    = (__nv_bfloat16*)sym_addr(g_Wb);
    float*         p_biasb = (float*)sym_addr(g_biasb);

    cudaFuncSetAttribute(mma_gemm_k<EPI_NONE>,  cudaFuncAttributeMaxDynamicSharedMemorySize, SMEM_TOTAL);
    cudaFuncSetAttribute(mma_gemm_k<EPI_SIG>,   cudaFuncAttributeMaxDynamicSharedMemorySize, SMEM_TOTAL);
    cudaFuncSetAttribute(mma_gemm_k<EPI_GATE>,  cudaFuncAttributeMaxDynamicSharedMemorySize, SMEM_TOTAL);
    cudaFuncSetAttribute(mma_gemm_k<EPI_RESID>, cudaFuncAttributeMaxDynamicSharedMemorySize, SMEM_TOTAL);

    auto cgrid = [](int n) { return (n + 255) / 256; };

    // launch order: #4 (1-based) is the val GEMM -> that's what the profiler captures
    rmsnorm_k<<<M_TOK, 256>>>(x, norm_w);                                     // 1
    f2bf_k<<<cgrid(2 * DI * D_MODEL), 256>>>(in_w, p_inw, 2 * DI * D_MODEL);  // 2

    dim3 gdIn(DI / BN, M_TOK / BM);
    mma_gemm_k<EPI_SIG><<<gdIn, 256, SMEM_TOTAL>>>(p_xn, p_inw, in_b, p_gate, DI,   // 3
                                                   nullptr, nullptr, D_MODEL);
    mma_gemm_k<EPI_NONE><<<gdIn, 256, SMEM_TOTAL>>>(p_xn, p_inw + (size_t)DI * D_MODEL,  // 4
                                                    in_b + DI, p_val, DI,
                                                    nullptr, nullptr, D_MODEL);

    f2bf_k<<<cgrid(DI * DI), 256>>>(fuse_w, p_fusew, DI * DI);
    f2bf_k<<<cgrid(D_MODEL * DI), 256>>>(out_w,  p_outw,  D_MODEL * DI);
    f2bf_k<<<cgrid(DH * DI), 256>>>(hb_w, p_hbw, DH * DI);
    transpose_pw_k<<<dim3(DI / 32, DI / 32), dim3(32, 8)>>>(pw_w);

    conv_fused_k<<<dim3(DI / CD, L_SEQ / CL, 4), 256>>>(dwa_k, dwa_b, sym_k, sym_b);

    // folded weight precomputes
    compute_T_k<<<DH, 128>>>(Bm, ha_w);
    compute_Wa_k<<<(DH * DI) / 256, 256>>>(A);
    mma_gemm_k<EPI_NONE><<<dim3(DI / BN, DH / BM), 256, SMEM_TOTAL>>>(
        p_hbw, p_pwT, nullptr, p_Wb, DI, nullptr, nullptr, DI);
    bias_b_k<<<DH, 256>>>(hb_w, pw_b, hb_b);

    // half projections -> concat into g_y
    dim3 gdH(DH / BN, M_TOK / BM);
    mma_gemm_k<EPI_NONE><<<gdH, 256, SMEM_TOTAL>>>(p_ca, p_Wa, ha_b, p_y, DI,
                                                   nullptr, nullptr, DI);
    mma_gemm_k<EPI_NONE><<<gdH, 256, SMEM_TOTAL>>>(p_cb, p_Wb, p_biasb, p_y + DH, DI,
                                                   nullptr, nullptr, DI);

    // fuse (+ gate multiply)
    mma_gemm_k<EPI_GATE><<<dim3(DI / BN, M_TOK / BM), 256, SMEM_TOTAL>>>(
        p_y, p_fusew, fuse_b, p_f, DI, p_gate, nullptr, DI);

    // out projection (+ residual), fp32 output
    mma_gemm_k<EPI_RESID><<<dim3(D_MODEL / BN, M_TOK / BM), 256, SMEM_TOTAL>>>(
        p_f, p_outw, out_b, d_out, D_MODEL, nullptr, x, DI);
}

// round 9
// speedup vs baseline: 1.0414x; 1.0154x over previous
#include <cuda_runtime.h>
#include <cuda_bf16.h>
#include <cstdint>

#define M_TOK   16384
#define L_SEQ   4096
#define D_MODEL 1024
#define DI      2048
#define DS      16
#define DH      1024

// ---------------- mma.sync GEMM tiling ----------------
// CTA 128x128, 4 warps (2x2), warp tile 64x64, BK=32, 3-stage cp.async, 3 CTAs/SM
#define BM 128
#define BN 128
#define BK 32
#define NSTAGE 3
#define PITCH 40                      // bf16 elems per smem row (80B) -> conflict-free ldmatrix
#define STAGE_BYTES (128 * PITCH * 2) // 10240 per tile
#define SMEM_TOTAL (NSTAGE * 2 * STAGE_BYTES)  // 61440

// ---------------- scratch (device globals) ----------------
__device__ __nv_bfloat16 g_xn  [(size_t)M_TOK * D_MODEL];
__device__ __nv_bfloat16 g_gate[(size_t)M_TOK * DI];
__device__ __nv_bfloat16 g_val [(size_t)M_TOK * DI];
__device__ __nv_bfloat16 g_ca  [(size_t)M_TOK * DI];
__device__ __nv_bfloat16 g_cb  [(size_t)M_TOK * DI];
__device__ __nv_bfloat16 g_y   [(size_t)M_TOK * DI];
__device__ __nv_bfloat16 g_f   [(size_t)M_TOK * DI];

__device__ __nv_bfloat16 g_inw  [(size_t)2 * DI * D_MODEL];
__device__ __nv_bfloat16 g_fusew[(size_t)DI * DI];
__device__ __nv_bfloat16 g_outw [(size_t)D_MODEL * DI];
__device__ __nv_bfloat16 g_hbw  [(size_t)DH * DI];
__device__ __nv_bfloat16 g_pwT  [(size_t)DI * DI];
__device__ __nv_bfloat16 g_Wa   [(size_t)DH * DI];
__device__ __nv_bfloat16 g_Wb   [(size_t)DH * DI];
__device__ float         g_T    [DS * DH];
__device__ float         g_biasb[DH];

// ---------------- PTX helpers ----------------
__device__ __forceinline__ uint32_t smem_u32(const void* p) {
    uint32_t a;
    asm("{ .reg .u64 t; cvta.to.shared.u64 t, %1; cvt.u32.u64 %0, t; }" : "=r"(a) : "l"(p));
    return a;
}
__device__ __forceinline__ void cpasync16(uint32_t dst, const void* src) {
    asm volatile("cp.async.cg.shared.global [%0], [%1], 16;" :: "r"(dst), "l"(src));
}
#define CP_COMMIT() asm volatile("cp.async.commit_group;" ::: "memory")
#define CP_WAIT1()  asm volatile("cp.async.wait_group 1;" ::: "memory")
#define CP_WAIT0()  asm volatile("cp.async.wait_group 0;" ::: "memory")

__device__ __forceinline__ void ldsm4(uint32_t* r, uint32_t addr) {
    asm volatile("ldmatrix.sync.aligned.m8n8.x4.shared.b16 {%0,%1,%2,%3}, [%4];"
        : "=r"(r[0]), "=r"(r[1]), "=r"(r[2]), "=r"(r[3]) : "r"(addr));
}
__device__ __forceinline__ void mma16816(float* d, const uint32_t* a, uint32_t b0, uint32_t b1) {
    asm volatile("mma.sync.aligned.m16n8k16.row.col.f32.bf16.bf16.f32 "
        "{%0,%1,%2,%3}, {%4,%5,%6,%7}, {%8,%9}, {%0,%1,%2,%3};"
        : "+f"(d[0]), "+f"(d[1]), "+f"(d[2]), "+f"(d[3])
        : "r"(a[0]), "r"(a[1]), "r"(a[2]), "r"(a[3]), "r"(b0), "r"(b1));
}

enum { EPI_NONE = 0, EPI_SIG = 1, EPI_GATE = 2, EPI_RESID = 3 };

// C[m,n] = sum_k X[m,k]*W[n,k]; X:(M,K) bf16 row-major, W:(N,K) bf16 row-major
template<int EPI>
__global__ void __launch_bounds__(128, 3) mma_gemm_k(
    const __nv_bfloat16* __restrict__ X, const __nv_bfloat16* __restrict__ W,
    const float* __restrict__ bias, void* __restrict__ outp, int out_stride,
    const __nv_bfloat16* __restrict__ gate, const float* __restrict__ resid,
    int K)
{
    extern __shared__ char smem[];
    uint32_t sA = smem_u32(smem);
    uint32_t sB = sA + NSTAGE * STAGE_BYTES;
    int tid = threadIdx.x, warp = tid >> 5, lane = tid & 31;
    int wm = warp >> 1, wn = warp & 1;           // 2 x 2 warp grid, warp tile 64x64
    int bm = blockIdx.y * BM, bn = blockIdx.x * BN;
    int NC = K / BK;

    // acc[mi][nj][4]: mi over 4 m16 rows, nj over 8 n8 cols
    float acc[4][8][4];
    #pragma unroll
    for (int mi = 0; mi < 4; mi++)
        #pragma unroll
        for (int nj = 0; nj < 8; nj++)
            #pragma unroll
            for (int e = 0; e < 4; e++) acc[mi][nj][e] = 0.f;

    // stage: A 128x32 + B 128x32, 16B chunks; 128 threads x 4 chunks per tile
    auto stage_load = [&](int st, int c) {
        uint32_t a = sA + st * STAGE_BYTES;
        uint32_t b = sB + st * STAGE_BYTES;
        int k0 = c * BK;
        #pragma unroll
        for (int it = 0; it < 4; it++) {
            int id = tid + it * 128;
            int r = id >> 2, s = id & 3;
            uint32_t off = (uint32_t)(r * PITCH + s * 8) * 2;
            cpasync16(a + off, X + (size_t)(bm + r) * K + k0 + s * 8);
            cpasync16(b + off, W + (size_t)(bn + r) * K + k0 + s * 8);
        }
    };

    #pragma unroll
    for (int c = 0; c < NSTAGE - 1; c++) {
        stage_load(c, c);
        CP_COMMIT();
    }

    // ldmatrix lane addressing (x4 form: 16 rows x 16B)
    int lrow = lane & 15;
    int lcol8 = (lane >> 4) * 8;
    uint32_t aRow = (uint32_t)((wm * 64 + lrow) * PITCH + lcol8) * 2;
    uint32_t bRow = (uint32_t)((wn * 64 + lrow) * PITCH + lcol8) * 2;

    for (int c = 0; c < NC; c++) {
        int st = c % NSTAGE;
        CP_WAIT1();
        __syncthreads();
        if (c + NSTAGE - 1 < NC) stage_load((c + NSTAGE - 1) % NSTAGE, c + NSTAGE - 1);
        CP_COMMIT();

        uint32_t aBase = sA + st * STAGE_BYTES + aRow;
        uint32_t bBase = sB + st * STAGE_BYTES + bRow;

        #pragma unroll
        for (int kk = 0; kk < 2; kk++) {
            // per-kk fragments: A 4x ldsm4, B 4x ldsm4 -> 32 HMMA
            uint32_t af[4][4], bf[4][4];
            #pragma unroll
            for (int mi = 0; mi < 4; mi++)
                ldsm4(af[mi], aBase + (uint32_t)(mi * 16 * PITCH + kk * 16) * 2);
            #pragma unroll
            for (int bi = 0; bi < 4; bi++)
                ldsm4(bf[bi], bBase + (uint32_t)(bi * 16 * PITCH + kk * 16) * 2);
            // bf[bi]: regs {0,2} = n8 group 2*bi (k0-7, k8-15), {1,3} = n8 group 2*bi+1
            #pragma unroll
            for (int mi = 0; mi < 4; mi++)
                #pragma unroll
                for (int nj = 0; nj < 8; nj++) {
                    int bi = nj >> 1, sel = nj & 1;
                    mma16816(acc[mi][nj], af[mi], bf[bi][sel], bf[bi][sel + 2]);
                }
        }
    }
    CP_WAIT0();

    // -------- register epilogue --------
    #pragma unroll
    for (int mi = 0; mi < 4; mi++) {
        #pragma unroll
        for (int nj = 0; nj < 8; nj++) {
            int gn = bn + wn * 64 + nj * 8 + (lane & 3) * 2;
            float b0 = 0.f, b1 = 0.f;
            if (bias) { b0 = bias[gn]; b1 = bias[gn + 1]; }
            #pragma unroll
            for (int h = 0; h < 2; h++) {
                int gm = bm + wm * 64 + mi * 16 + (lane >> 2) + h * 8;
                float v0 = acc[mi][nj][h * 2 + 0] + b0;
                float v1 = acc[mi][nj][h * 2 + 1] + b1;
                if (EPI == EPI_SIG) {
                    v0 = 1.f / (1.f + __expf(-v0));
                    v1 = 1.f / (1.f + __expf(-v1));
                }
                if (EPI == EPI_GATE) {
                    __nv_bfloat162 g2 = *(const __nv_bfloat162*)(gate + (size_t)gm * DI + gn);
                    v0 *= __bfloat162float(g2.x);
                    v1 *= __bfloat162float(g2.y);
                }
                if (EPI == EPI_RESID) {
                    const float* rp = resid + (size_t)gm * out_stride + gn;
                    float* op = (float*)outp + (size_t)gm * out_stride + gn;
                    float2 r2 = *(const float2*)rp;
                    float2 o2; o2.x = v0 + r2.x; o2.y = v1 + r2.y;
                    *(float2*)op = o2;
                } else {
                    __nv_bfloat16* op = (__nv_bfloat16*)outp + (size_t)gm * out_stride + gn;
                    *(__nv_bfloat162*)op = __floats2bfloat162_rn(v0, v1);
                }
            }
        }
    }
}

// ---------------- small kernels ----------------
__global__ void f2bf_k(const float* __restrict__ s, __nv_bfloat16* __restrict__ d, int n) {
    int i = blockIdx.x * 256 + threadIdx.x;
    if (i < n) d[i] = __float2bfloat16(s[i]);
}

__global__ void rmsnorm_k(const float* __restrict__ x, const float* __restrict__ w) {
    int row = blockIdx.x;
    int tid = threadIdx.x;
    const float* xr = x + (size_t)row * D_MODEL;
    float s = 0.f;
    for (int i = tid; i < D_MODEL; i += 256) { float v = xr[i]; s += v * v; }
    __shared__ float red[256];
    red[tid] = s; __syncthreads();
    for (int o = 128; o > 0; o >>= 1) {
        if (tid < o) red[tid] += red[tid + o];
        __syncthreads();
    }
    float scale = rsqrtf(red[0] / (float)D_MODEL + 1e-6f);
    for (int i = tid; i < D_MODEL; i += 256)
        g_xn[(size_t)row * D_MODEL + i] = __float2bfloat16(xr[i] * w[i] * scale);
}

// 32x32 tiled transpose: g_pwT[c][o] = pw_w[o][c], fp32 -> bf16
__global__ void transpose_pw_k(const float* __restrict__ src) {
    __shared__ float t[32][33];
    int bx = blockIdx.x * 32, by = blockIdx.y * 32;
    int tx = threadIdx.x, ty = threadIdx.y;
    #pragma unroll
    for (int i = 0; i < 32; i += 8)
        t[ty + i][tx] = src[(size_t)(by + ty + i) * DI + bx + tx];
    __syncthreads();
    #pragma unroll
    for (int i = 0; i < 32; i += 8)
        g_pwT[(size_t)(bx + ty + i) * DI + by + tx] = __float2bfloat16(t[tx][ty + i]);
}

// fused depthwise convs: a (4-tap, pad 1,2) and b = silu(9-tap, pad 4,4)
#define CL 128
#define CD 64
__global__ void __launch_bounds__(256) conv_fused_k(
    const float* __restrict__ ka, const float* __restrict__ ba,
    const float* __restrict__ ks, const float* __restrict__ bs)
{
    __shared__ __nv_bfloat16 sv[CL + 8][CD];
    int d0 = blockIdx.x * CD;
    int l0 = blockIdx.y * CL;
    int b  = blockIdx.z;
    const __nv_bfloat16* vb = g_val + (size_t)b * L_SEQ * DI;
    int tid = threadIdx.x;
    for (int i = tid; i < (CL + 8) * 8; i += 256) {
        int r = i >> 3, s = i & 7;
        int l = l0 - 4 + r;
        uint4 v = make_uint4(0, 0, 0, 0);
        if (l >= 0 && l < L_SEQ)
            v = *(const uint4*)(vb + (size_t)l * DI + d0 + s * 8);
        *(uint4*)(&sv[r][s * 8]) = v;
    }
    __syncthreads();
    int d = tid & (CD - 1);
    int lw = tid >> 6;
    float wa[4], w9[9];
    #pragma unroll
    for (int j = 0; j < 4; j++) wa[j] = ka[(d0 + d) * 4 + j];
    #pragma unroll
    for (int j = 0; j < 9; j++) w9[j] = ks[(d0 + d) * 9 + j];
    float bav = ba[d0 + d], bsv = bs[d0 + d];
    for (int li = 0; li < CL / 4; li++) {
        int l = lw * (CL / 4) + li;
        float aa = bav, ab = bsv;
        #pragma unroll
        for (int j = 0; j < 4; j++) aa += __bfloat162float(sv[l + 3 + j][d]) * wa[j];
        #pragma unroll
        for (int j = 0; j < 9; j++) ab += __bfloat162float(sv[l + j][d]) * w9[j];
        size_t o = ((size_t)b * L_SEQ + l0 + l) * DI + d0 + d;
        g_ca[o] = __float2bfloat16(aa);
        float sg = 1.f / (1.f + __expf(-ab));
        g_cb[o] = __float2bfloat16(ab * sg);
    }
}

// T[s][n] = sum_d Bm[s,d] * ha_w[n,d]
__global__ void compute_T_k(const float* __restrict__ Bm, const float* __restrict__ haw) {
    int n = blockIdx.x;
    int tid = threadIdx.x;
    float acc[DS];
    #pragma unroll
    for (int s = 0; s < DS; s++) acc[s] = 0.f;
    for (int d = tid; d < DI; d += 128) {
        float h = haw[(size_t)n * DI + d];
        #pragma unroll
        for (int s = 0; s < DS; s++) acc[s] += h * Bm[s * DI + d];
    }
    __shared__ float red[DS * 128];
    #pragma unroll
    for (int s = 0; s < DS; s++) red[s * 128 + tid] = acc[s];
    __syncthreads();
    if (tid < DS) {
        float t = 0.f;
        for (int i = 0; i < 128; i++) t += red[tid * 128 + i];
        g_T[tid * DH + n] = t;
    }
}

// Wa[n][k] = sum_s A[k,s] * T[s][n]
__global__ void compute_Wa_k(const float* __restrict__ A) {
    int idx = blockIdx.x * 256 + threadIdx.x;
    int k = idx & (DI - 1);
    int n = idx >> 11;
    float acc = 0.f;
    #pragma unroll
    for (int s = 0; s < DS; s++) acc += A[k * DS + s] * g_T[s * DH + n];
    g_Wa[(size_t)n * DI + k] = __float2bfloat16(acc);
}

// bias_b[n] = hb_b[n] + sum_d hb_w[n,d]*pw_b[d]
__global__ void bias_b_k(const float* __restrict__ hbw, const float* __restrict__ pwb,
                         const float* __restrict__ hbb) {
    int n = blockIdx.x;
    int tid = threadIdx.x;
    float a = 0.f;
    for (int d = tid; d < DI; d += 256) a += hbw[(size_t)n * DI + d] * pwb[d];
    __shared__ float red[256];
    red[tid] = a; __syncthreads();
    for (int o = 128; o > 0; o >>= 1) {
        if (tid < o) red[tid] += red[tid + o];
        __syncthreads();
    }
    if (tid == 0) g_biasb[n] = red[0] + hbb[n];
}

// ---------------- launch ----------------
static void* sym_addr(const void* s) {
    void* p = nullptr;
    cudaGetSymbolAddress(&p, s);
    return p;
}

extern "C" void kernel_launch(void* const* d_in, const int* in_sizes, int n_in,
                              void* d_out, int out_size) {
    const float* x      = (const float*)d_in[0];
    const float* norm_w = (const float*)d_in[1];
    const float* in_w   = (const float*)d_in[2];
    const float* in_b   = (const float*)d_in[3];
    const float* dwa_k  = (const float*)d_in[4];
    const float* dwa_b  = (const float*)d_in[5];
    const float* A      = (const float*)d_in[6];
    const float* Bm     = (const float*)d_in[7];
    const float* sym_k  = (const float*)d_in[8];
    const float* sym_b  = (const float*)d_in[9];
    const float* pw_w   = (const float*)d_in[10];
    const float* pw_b   = (const float*)d_in[11];
    const float* ha_w   = (const float*)d_in[12];
    const float* ha_b   = (const float*)d_in[13];
    const float* hb_w   = (const float*)d_in[14];
    const float* hb_b   = (const float*)d_in[15];
    const float* fuse_w = (const float*)d_in[16];
    const float* fuse_b = (const float*)d_in[17];
    const float* out_w  = (const float*)d_in[18];
    const float* out_b  = (const float*)d_in[19];

    __nv_bfloat16* p_xn    = (__nv_bfloat16*)sym_addr(g_xn);
    __nv_bfloat16* p_gate  = (__nv_bfloat16*)sym_addr(g_gate);
    __nv_bfloat16* p_ca    = (__nv_bfloat16*)sym_addr(g_ca);
    __nv_bfloat16* p_cb    = (__nv_bfloat16*)sym_addr(g_cb);
    __nv_bfloat16* p_val   = (__nv_bfloat16*)sym_addr(g_val);
    __nv_bfloat16* p_y     = (__nv_bfloat16*)sym_addr(g_y);
    __nv_bfloat16* p_f     = (__nv_bfloat16*)sym_addr(g_f);
    __nv_bfloat16* p_inw   = (__nv_bfloat16*)sym_addr(g_inw);
    __nv_bfloat16* p_fusew = (__nv_bfloat16*)sym_addr(g_fusew);
    __nv_bfloat16* p_outw  = (__nv_bfloat16*)sym_addr(g_outw);
    __nv_bfloat16* p_hbw   = (__nv_bfloat16*)sym_addr(g_hbw);
    __nv_bfloat16* p_pwT   = (__nv_bfloat16*)sym_addr(g_pwT);
    __nv_bfloat16* p_Wa    = (__nv_bfloat16*)sym_addr(g_Wa);
    __nv_bfloat16* p_Wb    = (__nv_bfloat16*)sym_addr(g_Wb);
    float*         p_biasb = (float*)sym_addr(g_biasb);

    cudaFuncSetAttribute(mma_gemm_k<EPI_NONE>,  cudaFuncAttributeMaxDynamicSharedMemorySize, SMEM_TOTAL);
    cudaFuncSetAttribute(mma_gemm_k<EPI_SIG>,   cudaFuncAttributeMaxDynamicSharedMemorySize, SMEM_TOTAL);
    cudaFuncSetAttribute(mma_gemm_k<EPI_GATE>,  cudaFuncAttributeMaxDynamicSharedMemorySize, SMEM_TOTAL);
    cudaFuncSetAttribute(mma_gemm_k<EPI_RESID>, cudaFuncAttributeMaxDynamicSharedMemorySize, SMEM_TOTAL);

    auto cgrid = [](int n) { return (n + 255) / 256; };

    // launch order: #4 (1-based) is the val GEMM -> that's what the profiler captures
    rmsnorm_k<<<M_TOK, 256>>>(x, norm_w);                                     // 1
    f2bf_k<<<cgrid(2 * DI * D_MODEL), 256>>>(in_w, p_inw, 2 * DI * D_MODEL);  // 2

    dim3 gdIn(DI / BN, M_TOK / BM);
    mma_gemm_k<EPI_SIG><<<gdIn, 128, SMEM_TOTAL>>>(p_xn, p_inw, in_b, p_gate, DI,   // 3
                                                   nullptr, nullptr, D_MODEL);
    mma_gemm_k<EPI_NONE><<<gdIn, 128, SMEM_TOTAL>>>(p_xn, p_inw + (size_t)DI * D_MODEL,  // 4
                                                    in_b + DI, p_val, DI,
                                                    nullptr, nullptr, D_MODEL);

    f2bf_k<<<cgrid(DI * DI), 256>>>(fuse_w, p_fusew, DI * DI);
    f2bf_k<<<cgrid(D_MODEL * DI), 256>>>(out_w,  p_outw,  D_MODEL * DI);
    f2bf_k<<<cgrid(DH * DI), 256>>>(hb_w, p_hbw, DH * DI);
    transpose_pw_k<<<dim3(DI / 32, DI / 32), dim3(32, 8)>>>(pw_w);

    conv_fused_k<<<dim3(DI / CD, L_SEQ / CL, 4), 256>>>(dwa_k, dwa_b, sym_k, sym_b);

    // folded weight precomputes
    compute_T_k<<<DH, 128>>>(Bm, ha_w);
    compute_Wa_k<<<(DH * DI) / 256, 256>>>(A);
    mma_gemm_k<EPI_NONE><<<dim3(DI / BN, DH / BM), 128, SMEM_TOTAL>>>(
        p_hbw, p_pwT, nullptr, p_Wb, DI, nullptr, nullptr, DI);
    bias_b_k<<<DH, 256>>>(hb_w, pw_b, hb_b);

    // half projections -> concat into g_y
    dim3 gdH(DH / BN, M_TOK / BM);
    mma_gemm_k<EPI_NONE><<<gdH, 128, SMEM_TOTAL>>>(p_ca, p_Wa, ha_b, p_y, DI,
                                                   nullptr, nullptr, DI);
    mma_gemm_k<EPI_NONE><<<gdH, 128, SMEM_TOTAL>>>(p_cb, p_Wb, p_biasb, p_y + DH, DI,
                                                   nullptr, nullptr, DI);

    // fuse (+ gate multiply)
    mma_gemm_k<EPI_GATE><<<dim3(DI / BN, M_TOK / BM), 128, SMEM_TOTAL>>>(
        p_y, p_fusew, fuse_b, p_f, DI, p_gate, nullptr, DI);

    // out projection (+ residual), fp32 output
    mma_gemm_k<EPI_RESID><<<dim3(D_MODEL / BN, M_TOK / BM), 128, SMEM_TOTAL>>>(
        p_f, p_outw, out_b, d_out, D_MODEL, nullptr, x, DI);
}

// round 14
// speedup vs baseline: 1.2687x; 1.2183x over previous
#include <cuda_runtime.h>
#include <cuda_bf16.h>
#include <cstdint>

#define M_TOK   16384
#define L_SEQ   4096
#define D_MODEL 1024
#define DI      2048
#define DS      16
#define DH      1024
#define YK      1056          // concat K: 16 a1 + 16 pad + 1024 b_h

// ---------------- mma.sync GEMM tiling (R3 config) ----------------
#define BM 128
#define BN 128
#define BK 32
#define NSTAGE 4
#define PITCH 40                      // bf16 elems per smem row (80B) -> conflict-free ldmatrix
#define STAGE_BYTES (128 * PITCH * 2) // 10240 per tile
#define SMEM_TOTAL (NSTAGE * 2 * STAGE_BYTES)  // 81920

// ---------------- scratch (device globals) ----------------
__device__ __nv_bfloat16 g_xn  [(size_t)M_TOK * D_MODEL];
__device__ __nv_bfloat16 g_gate[(size_t)M_TOK * DI];
__device__ __nv_bfloat16 g_val [(size_t)M_TOK * DI];
__device__ __nv_bfloat16 g_ca  [(size_t)M_TOK * DI];
__device__ __nv_bfloat16 g_cb  [(size_t)M_TOK * DI];
__device__ __nv_bfloat16 g_yc  [(size_t)M_TOK * YK];   // [a1 | pad | b_h]
__device__ __nv_bfloat16 g_f   [(size_t)M_TOK * DI];

__device__ __nv_bfloat16 g_inw  [(size_t)2 * DI * D_MODEL];
__device__ __nv_bfloat16 g_outw [(size_t)D_MODEL * DI];
__device__ __nv_bfloat16 g_hbw  [(size_t)DH * DI];
__device__ __nv_bfloat16 g_pwT  [(size_t)DI * DI];
__device__ __nv_bfloat16 g_Wb   [(size_t)DH * DI];
__device__ __nv_bfloat16 g_wf   [(size_t)DI * YK];     // y-GEMM weight (2048 x 1056)
__device__ float         g_T    [DS * DH];
__device__ float         g_biasb[DH];
__device__ float         g_biasy[DI];

// ---------------- PTX helpers ----------------
__device__ __forceinline__ uint32_t smem_u32(const void* p) {
    uint32_t a;
    asm("{ .reg .u64 t; cvta.to.shared.u64 t, %1; cvt.u32.u64 %0, t; }" : "=r"(a) : "l"(p));
    return a;
}
__device__ __forceinline__ void cpasync16(uint32_t dst, const void* src) {
    asm volatile("cp.async.cg.shared.global [%0], [%1], 16;" :: "r"(dst), "l"(src));
}
#define CP_COMMIT() asm volatile("cp.async.commit_group;" ::: "memory")
#define CP_WAIT2()  asm volatile("cp.async.wait_group 2;" ::: "memory")
#define CP_WAIT0()  asm volatile("cp.async.wait_group 0;" ::: "memory")

__device__ __forceinline__ void ldsm4(uint32_t* r, uint32_t addr) {
    asm volatile("ldmatrix.sync.aligned.m8n8.x4.shared.b16 {%0,%1,%2,%3}, [%4];"
        : "=r"(r[0]), "=r"(r[1]), "=r"(r[2]), "=r"(r[3]) : "r"(addr));
}
__device__ __forceinline__ void ldsm2(uint32_t* r, uint32_t addr) {
    asm volatile("ldmatrix.sync.aligned.m8n8.x2.shared.b16 {%0,%1}, [%2];"
        : "=r"(r[0]), "=r"(r[1]) : "r"(addr));
}
__device__ __forceinline__ void mma16816(float* d, const uint32_t* a, const uint32_t* b) {
    asm volatile("mma.sync.aligned.m16n8k16.row.col.f32.bf16.bf16.f32 "
        "{%0,%1,%2,%3}, {%4,%5,%6,%7}, {%8,%9}, {%0,%1,%2,%3};"
        : "+f"(d[0]), "+f"(d[1]), "+f"(d[2]), "+f"(d[3])
        : "r"(a[0]), "r"(a[1]), "r"(a[2]), "r"(a[3]), "r"(b[0]), "r"(b[1]));
}

enum { EPI_NONE = 0, EPI_SIG = 1, EPI_GATE = 2, EPI_RESID = 3 };

// C[m,n] = sum_k X[m,k]*W[n,k]; X:(M,K) bf16 row-major, W:(N,K) bf16 row-major
template<int EPI>
__global__ void __launch_bounds__(256, 2) mma_gemm_k(
    const __nv_bfloat16* __restrict__ X, const __nv_bfloat16* __restrict__ W,
    const float* __restrict__ bias, void* __restrict__ outp, int out_stride,
    const __nv_bfloat16* __restrict__ gate, const float* __restrict__ resid,
    int K)
{
    extern __shared__ char smem[];
    uint32_t sA = smem_u32(smem);
    uint32_t sB = sA + NSTAGE * STAGE_BYTES;
    int tid = threadIdx.x, warp = tid >> 5, lane = tid & 31;
    int wm = warp >> 2, wn = warp & 3;           // 2 x 4 warp grid, warp tile 64x32
    int bm = blockIdx.y * BM, bn = blockIdx.x * BN;
    int NC = K / BK;

    float acc[4][4][4];
    #pragma unroll
    for (int mi = 0; mi < 4; mi++)
        #pragma unroll
        for (int ni = 0; ni < 4; ni++)
            #pragma unroll
            for (int e = 0; e < 4; e++) acc[mi][ni][e] = 0.f;

    auto stage_load = [&](int st, int c) {
        uint32_t a = sA + st * STAGE_BYTES;
        uint32_t b = sB + st * STAGE_BYTES;
        int k0 = c * BK;
        #pragma unroll
        for (int it = 0; it < 2; it++) {
            int id = tid + it * 256;
            int r = id >> 2, s = id & 3;
            uint32_t off = (uint32_t)(r * PITCH + s * 8) * 2;
            cpasync16(a + off, X + (size_t)(bm + r) * K + k0 + s * 8);
            cpasync16(b + off, W + (size_t)(bn + r) * K + k0 + s * 8);
        }
    };

    #pragma unroll
    for (int c = 0; c < NSTAGE - 1; c++) {
        stage_load(c, c);
        CP_COMMIT();
    }

    for (int c = 0; c < NC; c++) {
        int st = c & (NSTAGE - 1);
        CP_WAIT2();
        __syncthreads();
        if (c + NSTAGE - 1 < NC) stage_load((c + NSTAGE - 1) & (NSTAGE - 1), c + NSTAGE - 1);
        CP_COMMIT();

        uint32_t aBase = sA + st * STAGE_BYTES;
        uint32_t bBase = sB + st * STAGE_BYTES;
        #pragma unroll
        for (int kk = 0; kk < 2; kk++) {
            uint32_t af[4][4], bf[4][2];
            #pragma unroll
            for (int mi = 0; mi < 4; mi++) {
                int row = wm * 64 + mi * 16 + (lane & 15);
                ldsm4(af[mi], aBase + (uint32_t)(row * PITCH + kk * 16 + (lane >> 4) * 8) * 2);
            }
            #pragma unroll
            for (int ni = 0; ni < 4; ni++) {
                int row = wn * 32 + ni * 8 + (lane & 7);
                ldsm2(bf[ni], bBase + (uint32_t)(row * PITCH + kk * 16 + ((lane >> 3) & 1) * 8) * 2);
            }
            #pragma unroll
            for (int mi = 0; mi < 4; mi++)
                #pragma unroll
                for (int ni = 0; ni < 4; ni++)
                    mma16816(acc[mi][ni], af[mi], bf[ni]);
        }
    }
    CP_WAIT0();

    // -------- register epilogue --------
    #pragma unroll
    for (int mi = 0; mi < 4; mi++) {
        #pragma unroll
        for (int ni = 0; ni < 4; ni++) {
            int gn = bn + wn * 32 + ni * 8 + (lane & 3) * 2;
            float b0 = 0.f, b1 = 0.f;
            if (bias) { b0 = bias[gn]; b1 = bias[gn + 1]; }
            #pragma unroll
            for (int h = 0; h < 2; h++) {
                int gm = bm + wm * 64 + mi * 16 + (lane >> 2) + h * 8;
                float v0 = acc[mi][ni][h * 2 + 0] + b0;
                float v1 = acc[mi][ni][h * 2 + 1] + b1;
                if (EPI == EPI_SIG) {
                    v0 = 1.f / (1.f + __expf(-v0));
                    v1 = 1.f / (1.f + __expf(-v1));
                }
                if (EPI == EPI_GATE) {
                    __nv_bfloat162 g2 = *(const __nv_bfloat162*)(gate + (size_t)gm * DI + gn);
                    v0 *= __bfloat162float(g2.x);
                    v1 *= __bfloat162float(g2.y);
                }
                if (EPI == EPI_RESID) {
                    const float* rp = resid + (size_t)gm * out_stride + gn;
                    float* op = (float*)outp + (size_t)gm * out_stride + gn;
                    float2 r2 = *(const float2*)rp;
                    float2 o2; o2.x = v0 + r2.x; o2.y = v1 + r2.y;
                    *(float2*)op = o2;
                } else {
                    __nv_bfloat16* op = (__nv_bfloat16*)outp + (size_t)gm * out_stride + gn;
                    *(__nv_bfloat162*)op = __floats2bfloat162_rn(v0, v1);
                }
            }
        }
    }
}

// ---------------- small kernels ----------------
__global__ void f2bf_k(const float* __restrict__ s, __nv_bfloat16* __restrict__ d, int n) {
    int i = blockIdx.x * 256 + threadIdx.x;
    if (i < n) d[i] = __float2bfloat16(s[i]);
}

__global__ void rmsnorm_k(const float* __restrict__ x, const float* __restrict__ w) {
    int row = blockIdx.x;
    int tid = threadIdx.x;
    const float* xr = x + (size_t)row * D_MODEL;
    float s = 0.f;
    for (int i = tid; i < D_MODEL; i += 256) { float v = xr[i]; s += v * v; }
    __shared__ float red[256];
    red[tid] = s; __syncthreads();
    for (int o = 128; o > 0; o >>= 1) {
        if (tid < o) red[tid] += red[tid + o];
        __syncthreads();
    }
    float scale = rsqrtf(red[0] / (float)D_MODEL + 1e-6f);
    for (int i = tid; i < D_MODEL; i += 256)
        g_xn[(size_t)row * D_MODEL + i] = __float2bfloat16(xr[i] * w[i] * scale);
}

// 32x32 tiled transpose: g_pwT[c][o] = pw_w[o][c], fp32 -> bf16
__global__ void transpose_pw_k(const float* __restrict__ src) {
    __shared__ float t[32][33];
    int bx = blockIdx.x * 32, by = blockIdx.y * 32;
    int tx = threadIdx.x, ty = threadIdx.y;
    #pragma unroll
    for (int i = 0; i < 32; i += 8)
        t[ty + i][tx] = src[(size_t)(by + ty + i) * DI + bx + tx];
    __syncthreads();
    #pragma unroll
    for (int i = 0; i < 32; i += 8)
        g_pwT[(size_t)(bx + ty + i) * DI + by + tx] = __float2bfloat16(t[tx][ty + i]);
}

// fused depthwise convs: a (4-tap, pad 1,2) and b = silu(9-tap, pad 4,4)
#define CL 128
#define CD 64
__global__ void __launch_bounds__(256) conv_fused_k(
    const float* __restrict__ ka, const float* __restrict__ ba,
    const float* __restrict__ ks, const float* __restrict__ bs)
{
    __shared__ __nv_bfloat16 sv[CL + 8][CD];
    int d0 = blockIdx.x * CD;
    int l0 = blockIdx.y * CL;
    int b  = blockIdx.z;
    const __nv_bfloat16* vb = g_val + (size_t)b * L_SEQ * DI;
    int tid = threadIdx.x;
    for (int i = tid; i < (CL + 8) * 8; i += 256) {
        int r = i >> 3, s = i & 7;
        int l = l0 - 4 + r;
        uint4 v = make_uint4(0, 0, 0, 0);
        if (l >= 0 && l < L_SEQ)
            v = *(const uint4*)(vb + (size_t)l * DI + d0 + s * 8);
        *(uint4*)(&sv[r][s * 8]) = v;
    }
    __syncthreads();
    int d = tid & (CD - 1);
    int lw = tid >> 6;
    float wa[4], w9[9];
    #pragma unroll
    for (int j = 0; j < 4; j++) wa[j] = ka[(d0 + d) * 4 + j];
    #pragma unroll
    for (int j = 0; j < 9; j++) w9[j] = ks[(d0 + d) * 9 + j];
    float bav = ba[d0 + d], bsv = bs[d0 + d];
    for (int li = 0; li < CL / 4; li++) {
        int l = lw * (CL / 4) + li;
        float aa = bav, ab = bsv;
        #pragma unroll
        for (int j = 0; j < 4; j++) aa += __bfloat162float(sv[l + 3 + j][d]) * wa[j];
        #pragma unroll
        for (int j = 0; j < 9; j++) ab += __bfloat162float(sv[l + j][d]) * w9[j];
        size_t o = ((size_t)b * L_SEQ + l0 + l) * DI + d0 + d;
        g_ca[o] = __float2bfloat16(aa);
        float sg = 1.f / (1.f + __expf(-ab));
        g_cb[o] = __float2bfloat16(ab * sg);
    }
}

// T[s][n] = sum_d Bm[s,d] * ha_w[n,d]   (16 x 1024)
__global__ void compute_T_k(const float* __restrict__ Bm, const float* __restrict__ haw) {
    int n = blockIdx.x;
    int tid = threadIdx.x;
    float acc[DS];
    #pragma unroll
    for (int s = 0; s < DS; s++) acc[s] = 0.f;
    for (int d = tid; d < DI; d += 128) {
        float h = haw[(size_t)n * DI + d];
        #pragma unroll
        for (int s = 0; s < DS; s++) acc[s] += h * Bm[s * DI + d];
    }
    __shared__ float red[DS * 128];
    #pragma unroll
    for (int s = 0; s < DS; s++) red[s * 128 + tid] = acc[s];
    __syncthreads();
    if (tid < DS) {
        float t = 0.f;
        for (int i = 0; i < 128; i++) t += red[tid * 128 + i];
        g_T[tid * DH + n] = t;
    }
}

// a1[m, 0:16] = sum_d ca[m,d] * A[d,s]; zero-pad cols 16..31. One warp per token.
__global__ void __launch_bounds__(256) a1_k(const float* __restrict__ A) {
    int warp = threadIdx.x >> 5, lane = threadIdx.x & 31;
    size_t m = (size_t)blockIdx.x * 8 + warp;
    const __nv_bfloat16* car = g_ca + m * DI;
    float acc[16];
    #pragma unroll
    for (int s = 0; s < 16; s++) acc[s] = 0.f;
    for (int d = lane; d < DI; d += 32) {
        float c = __bfloat162float(car[d]);
        const float4* Ar = (const float4*)(A + (size_t)d * 16);
        float4 a0 = Ar[0], a1v = Ar[1], a2 = Ar[2], a3 = Ar[3];
        acc[0]  += c * a0.x;  acc[1]  += c * a0.y;  acc[2]  += c * a0.z;  acc[3]  += c * a0.w;
        acc[4]  += c * a1v.x; acc[5]  += c * a1v.y; acc[6]  += c * a1v.z; acc[7]  += c * a1v.w;
        acc[8]  += c * a2.x;  acc[9]  += c * a2.y;  acc[10] += c * a2.z;  acc[11] += c * a2.w;
        acc[12] += c * a3.x;  acc[13] += c * a3.y;  acc[14] += c * a3.z;  acc[15] += c * a3.w;
    }
    #pragma unroll
    for (int s = 0; s < 16; s++)
        #pragma unroll
        for (int o = 16; o > 0; o >>= 1)
            acc[s] += __shfl_xor_sync(0xFFFFFFFFu, acc[s], o);
    if (lane == 0) {
        uint32_t pk[8];
        #pragma unroll
        for (int h = 0; h < 8; h++) {
            __nv_bfloat162 t = __floats2bfloat162_rn(acc[2 * h], acc[2 * h + 1]);
            pk[h] = *reinterpret_cast<uint32_t*>(&t);
        }
        uint4* dst = (uint4*)(g_yc + m * YK);
        dst[0] = make_uint4(pk[0], pk[1], pk[2], pk[3]);
        dst[1] = make_uint4(pk[4], pk[5], pk[6], pk[7]);
        dst[2] = make_uint4(0, 0, 0, 0);
        dst[3] = make_uint4(0, 0, 0, 0);
    }
}

// wf[n][s] = U[s][n] = sum_{t<1024} T[s,t] * fuse_w[n,t];  wf[n][16..31] = 0
__global__ void wf_u_k(const float* __restrict__ fw) {
    int n = blockIdx.x;
    int tid = threadIdx.x;   // 128
    float acc[DS];
    #pragma unroll
    for (int s = 0; s < DS; s++) acc[s] = 0.f;
    for (int t = tid; t < DH; t += 128) {
        float f = fw[(size_t)n * DI + t];
        #pragma unroll
        for (int s = 0; s < DS; s++) acc[s] += f * g_T[s * DH + t];
    }
    __shared__ float red[DS * 128];
    #pragma unroll
    for (int s = 0; s < DS; s++) red[s * 128 + tid] = acc[s];
    __syncthreads();
    if (tid < DS) {
        float t = 0.f;
        for (int i = 0; i < 128; i++) t += red[tid * 128 + i];
        g_wf[(size_t)n * YK + tid] = __float2bfloat16(t);
    } else if (tid < 32) {
        g_wf[(size_t)n * YK + tid] = __float2bfloat16(0.f);
    }
}

// wf[n][32+j] = fuse_w[n][1024+j]
__global__ void wf_copy_k(const float* __restrict__ fw) {
    int idx = blockIdx.x * 256 + threadIdx.x;      // DI * DH
    int n = idx >> 10, j = idx & 1023;
    g_wf[(size_t)n * YK + 32 + j] = __float2bfloat16(fw[(size_t)n * DI + DH + j]);
}

// biasy[n] = fuse_b[n] + sum_{t<1024} fuse_w[n,t] * ha_b[t]
__global__ void bias_y_k(const float* __restrict__ fw, const float* __restrict__ hab,
                         const float* __restrict__ fb) {
    int n = blockIdx.x;
    int tid = threadIdx.x;
    float a = 0.f;
    for (int t = tid; t < DH; t += 256) a += fw[(size_t)n * DI + t] * hab[t];
    __shared__ float red[256];
    red[tid] = a; __syncthreads();
    for (int o = 128; o > 0; o >>= 1) {
        if (tid < o) red[tid] += red[tid + o];
        __syncthreads();
    }
    if (tid == 0) g_biasy[n] = red[0] + fb[n];
}

// bias_b[n] = hb_b[n] + sum_d hb_w[n,d]*pw_b[d]
__global__ void bias_b_k(const float* __restrict__ hbw, const float* __restrict__ pwb,
                         const float* __restrict__ hbb) {
    int n = blockIdx.x;
    int tid = threadIdx.x;
    float a = 0.f;
    for (int d = tid; d < DI; d += 256) a += hbw[(size_t)n * DI + d] * pwb[d];
    __shared__ float red[256];
    red[tid] = a; __syncthreads();
    for (int o = 128; o > 0; o >>= 1) {
        if (tid < o) red[tid] += red[tid + o];
        __syncthreads();
    }
    if (tid == 0) g_biasb[n] = red[0] + hbb[n];
}

// ---------------- launch ----------------
static void* sym_addr(const void* s) {
    void* p = nullptr;
    cudaGetSymbolAddress(&p, s);
    return p;
}

extern "C" void kernel_launch(void* const* d_in, const int* in_sizes, int n_in,
                              void* d_out, int out_size) {
    const float* x      = (const float*)d_in[0];
    const float* norm_w = (const float*)d_in[1];
    const float* in_w   = (const float*)d_in[2];
    const float* in_b   = (const float*)d_in[3];
    const float* dwa_k  = (const float*)d_in[4];
    const float* dwa_b  = (const float*)d_in[5];
    const float* A      = (const float*)d_in[6];
    const float* Bm     = (const float*)d_in[7];
    const float* sym_k  = (const float*)d_in[8];
    const float* sym_b  = (const float*)d_in[9];
    const float* pw_w   = (const float*)d_in[10];
    const float* pw_b   = (const float*)d_in[11];
    const float* ha_w   = (const float*)d_in[12];
    const float* ha_b   = (const float*)d_in[13];
    const float* hb_w   = (const float*)d_in[14];
    const float* hb_b   = (const float*)d_in[15];
    const float* fuse_w = (const float*)d_in[16];
    const float* fuse_b = (const float*)d_in[17];
    const float* out_w  = (const float*)d_in[18];
    const float* out_b  = (const float*)d_in[19];

    __nv_bfloat16* p_xn    = (__nv_bfloat16*)sym_addr(g_xn);
    __nv_bfloat16* p_gate  = (__nv_bfloat16*)sym_addr(g_gate);
    __nv_bfloat16* p_ca    = (__nv_bfloat16*)sym_addr(g_ca);
    __nv_bfloat16* p_cb    = (__nv_bfloat16*)sym_addr(g_cb);
    __nv_bfloat16* p_val   = (__nv_bfloat16*)sym_addr(g_val);
    __nv_bfloat16* p_yc    = (__nv_bfloat16*)sym_addr(g_yc);
    __nv_bfloat16* p_f     = (__nv_bfloat16*)sym_addr(g_f);
    __nv_bfloat16* p_inw   = (__nv_bfloat16*)sym_addr(g_inw);
    __nv_bfloat16* p_outw  = (__nv_bfloat16*)sym_addr(g_outw);
    __nv_bfloat16* p_hbw   = (__nv_bfloat16*)sym_addr(g_hbw);
    __nv_bfloat16* p_pwT   = (__nv_bfloat16*)sym_addr(g_pwT);
    __nv_bfloat16* p_Wb    = (__nv_bfloat16*)sym_addr(g_Wb);
    __nv_bfloat16* p_wf    = (__nv_bfloat16*)sym_addr(g_wf);
    float*         p_biasb = (float*)sym_addr(g_biasb);
    float*         p_biasy = (float*)sym_addr(g_biasy);

    cudaFuncSetAttribute(mma_gemm_k<EPI_NONE>,  cudaFuncAttributeMaxDynamicSharedMemorySize, SMEM_TOTAL);
    cudaFuncSetAttribute(mma_gemm_k<EPI_SIG>,   cudaFuncAttributeMaxDynamicSharedMemorySize, SMEM_TOTAL);
    cudaFuncSetAttribute(mma_gemm_k<EPI_GATE>,  cudaFuncAttributeMaxDynamicSharedMemorySize, SMEM_TOTAL);
    cudaFuncSetAttribute(mma_gemm_k<EPI_RESID>, cudaFuncAttributeMaxDynamicSharedMemorySize, SMEM_TOTAL);

    auto cgrid = [](int n) { return (n + 255) / 256; };

    // launch order: #4 (1-based) = val GEMM -> profiled by ncu -s/-c
    rmsnorm_k<<<M_TOK, 256>>>(x, norm_w);                                     // 1
    f2bf_k<<<cgrid(2 * DI * D_MODEL), 256>>>(in_w, p_inw, 2 * DI * D_MODEL);  // 2

    dim3 gdIn(DI / BN, M_TOK / BM);
    mma_gemm_k<EPI_SIG><<<gdIn, 256, SMEM_TOTAL>>>(p_xn, p_inw, in_b, p_gate, DI,   // 3
                                                   nullptr, nullptr, D_MODEL);
    mma_gemm_k<EPI_NONE><<<gdIn, 256, SMEM_TOTAL>>>(p_xn, p_inw + (size_t)DI * D_MODEL,  // 4
                                                    in_b + DI, p_val, DI,
                                                    nullptr, nullptr, D_MODEL);

    f2bf_k<<<cgrid(DH * DI), 256>>>(hb_w, p_hbw, DH * DI);
    f2bf_k<<<cgrid(D_MODEL * DI), 256>>>(out_w, p_outw, D_MODEL * DI);
    transpose_pw_k<<<dim3(DI / 32, DI / 32), dim3(32, 8)>>>(pw_w);

    conv_fused_k<<<dim3(DI / CD, L_SEQ / CL, 4), 256>>>(dwa_k, dwa_b, sym_k, sym_b);

    // folded-weight precomputes
    compute_T_k<<<DH, 128>>>(Bm, ha_w);
    mma_gemm_k<EPI_NONE><<<dim3(DI / BN, DH / BM), 256, SMEM_TOTAL>>>(
        p_hbw, p_pwT, nullptr, p_Wb, DI, nullptr, nullptr, DI);      // Wb = hb_w @ pw_w
    bias_b_k<<<DH, 256>>>(hb_w, pw_b, hb_b);
    wf_u_k<<<DI, 128>>>(fuse_w);
    wf_copy_k<<<cgrid(DI * DH), 256>>>(fuse_w);
    bias_y_k<<<DI, 256>>>(fuse_w, ha_b, fuse_b);

    // a-branch through rank-16 bottleneck: a1 = ca @ A  (into yc cols 0..15)
    a1_k<<<M_TOK / 8, 256>>>(A);

    // b-branch: b_h = cb @ Wb + biasb  (into yc cols 32..1055)
    mma_gemm_k<EPI_NONE><<<dim3(DH / BN, M_TOK / BM), 256, SMEM_TOTAL>>>(
        p_cb, p_Wb, p_biasb, p_yc + 32, YK, nullptr, nullptr, DI);

    // fused y GEMM: y = [a1|b_h] @ wf^T + biasy, gated   (K=1056)
    mma_gemm_k<EPI_GATE><<<dim3(DI / BN, M_TOK / BM), 256, SMEM_TOTAL>>>(
        p_yc, p_wf, p_biasy, p_f, DI, p_gate, nullptr, YK);

    // out projection (+ residual), fp32 output
    mma_gemm_k<EPI_RESID><<<dim3(D_MODEL / BN, M_TOK / BM), 256, SMEM_TOTAL>>>(
        p_f, p_outw, out_b, d_out, D_MODEL, nullptr, x, DI);
}

// round 15
// speedup vs baseline: 1.3227x; 1.0425x over previous
#include <cuda_runtime.h>
#include <cuda_bf16.h>
#include <cuda_fp8.h>
#include <cstdint>

#define M_TOK   16384
#define L_SEQ   4096
#define D_MODEL 1024
#define DI      2048
#define DS      16
#define DH      1024
#define YK8     1088          // fp8 concat K: 16 a1 + 48 pad + 1024 b_h (64B-chunk aligned)

// scale factors (power-of-2)
#define S_XN  4.0f
#define S_W   128.0f
#define S_CB  64.0f
#define S_YC  64.0f
#define S_F   256.0f

// ---------------- bf16 GEMM tiling (Wb precompute only) ----------------
#define BM 128
#define BN 128
#define PITCH 40
#define STAGE_BYTES (128 * PITCH * 2)            // 10240
#define NSTAGE 4
#define SMEM_TOTAL (NSTAGE * 2 * STAGE_BYTES)    // 81920

// ---------------- fp8 GEMM tiling ----------------
#define QPITCH 80                                 // bytes per smem row
#define QSTAGE (128 * QPITCH)                     // 10240
#define QSMEM_TOTAL (NSTAGE * 2 * QSTAGE)         // 81920

// ---------------- scratch (device globals) ----------------
__device__ __align__(16) uint8_t g_xn8 [(size_t)M_TOK * D_MODEL];
__device__ __nv_bfloat16 g_gate[(size_t)M_TOK * DI];
__device__ __nv_bfloat16 g_val [(size_t)M_TOK * DI];
__device__ __nv_bfloat16 g_ca  [(size_t)M_TOK * DI];
__device__ __align__(16) uint8_t g_cb8 [(size_t)M_TOK * DI];
__device__ __align__(16) uint8_t g_yc8 [(size_t)M_TOK * YK8];
__device__ __align__(16) uint8_t g_f8  [(size_t)M_TOK * DI];

__device__ __align__(16) uint8_t g_inw8 [(size_t)2 * DI * D_MODEL];
__device__ __align__(16) uint8_t g_outw8[(size_t)D_MODEL * DI];
__device__ __align__(16) uint8_t g_Wb8  [(size_t)DH * DI];
__device__ __align__(16) uint8_t g_wf8  [(size_t)DI * YK8];
__device__ __nv_bfloat16 g_hbw  [(size_t)DH * DI];
__device__ __nv_bfloat16 g_pwT  [(size_t)DI * DI];
__device__ __nv_bfloat16 g_Wb   [(size_t)DH * DI];
__device__ float         g_T    [DS * DH];
__device__ float         g_biasb[DH];
__device__ float         g_biasy[DI];

// ---------------- PTX helpers ----------------
__device__ __forceinline__ uint32_t smem_u32(const void* p) {
    uint32_t a;
    asm("{ .reg .u64 t; cvta.to.shared.u64 t, %1; cvt.u32.u64 %0, t; }" : "=r"(a) : "l"(p));
    return a;
}
__device__ __forceinline__ void cpasync16(uint32_t dst, const void* src) {
    asm volatile("cp.async.cg.shared.global [%0], [%1], 16;" :: "r"(dst), "l"(src));
}
#define CP_COMMIT() asm volatile("cp.async.commit_group;" ::: "memory")
#define CP_WAIT2()  asm volatile("cp.async.wait_group 2;" ::: "memory")
#define CP_WAIT0()  asm volatile("cp.async.wait_group 0;" ::: "memory")

__device__ __forceinline__ void ldsm4(uint32_t* r, uint32_t addr) {
    asm volatile("ldmatrix.sync.aligned.m8n8.x4.shared.b16 {%0,%1,%2,%3}, [%4];"
        : "=r"(r[0]), "=r"(r[1]), "=r"(r[2]), "=r"(r[3]) : "r"(addr));
}
__device__ __forceinline__ void ldsm2(uint32_t* r, uint32_t addr) {
    asm volatile("ldmatrix.sync.aligned.m8n8.x2.shared.b16 {%0,%1}, [%2];"
        : "=r"(r[0]), "=r"(r[1]) : "r"(addr));
}
__device__ __forceinline__ void mma16816(float* d, const uint32_t* a, const uint32_t* b) {
    asm volatile("mma.sync.aligned.m16n8k16.row.col.f32.bf16.bf16.f32 "
        "{%0,%1,%2,%3}, {%4,%5,%6,%7}, {%8,%9}, {%0,%1,%2,%3};"
        : "+f"(d[0]), "+f"(d[1]), "+f"(d[2]), "+f"(d[3])
        : "r"(a[0]), "r"(a[1]), "r"(a[2]), "r"(a[3]), "r"(b[0]), "r"(b[1]));
}
__device__ __forceinline__ void qmma16832(float* d, const uint32_t* a, const uint32_t* b) {
    asm volatile("mma.sync.aligned.m16n8k32.row.col.f32.e4m3.e4m3.f32 "
        "{%0,%1,%2,%3}, {%4,%5,%6,%7}, {%8,%9}, {%0,%1,%2,%3};"
        : "+f"(d[0]), "+f"(d[1]), "+f"(d[2]), "+f"(d[3])
        : "r"(a[0]), "r"(a[1]), "r"(a[2]), "r"(a[3]), "r"(b[0]), "r"(b[1]));
}

__device__ __forceinline__ uint8_t f2fp8(float v) {
    return (uint8_t)__nv_cvt_float_to_fp8(v, __NV_SATFINITE, __NV_E4M3);
}
__device__ __forceinline__ uint16_t f2fp8x2(float a, float b) {
    return (uint16_t)__nv_cvt_float2_to_fp8x2(make_float2(a, b), __NV_SATFINITE, __NV_E4M3);
}

// ================= bf16 GEMM (Wb precompute only) =================
__global__ void __launch_bounds__(256, 2) mma_gemm_k(
    const __nv_bfloat16* __restrict__ X, const __nv_bfloat16* __restrict__ W,
    __nv_bfloat16* __restrict__ outp, int out_stride, int K)
{
    extern __shared__ char smem[];
    uint32_t sA = smem_u32(smem);
    uint32_t sB = sA + NSTAGE * STAGE_BYTES;
    int tid = threadIdx.x, warp = tid >> 5, lane = tid & 31;
    int wm = warp >> 2, wn = warp & 3;
    int bm = blockIdx.y * BM, bn = blockIdx.x * BN;
    int NC = K / 32;

    float acc[4][4][4];
    #pragma unroll
    for (int mi = 0; mi < 4; mi++)
        #pragma unroll
        for (int ni = 0; ni < 4; ni++)
            #pragma unroll
            for (int e = 0; e < 4; e++) acc[mi][ni][e] = 0.f;

    auto stage_load = [&](int st, int c) {
        uint32_t a = sA + st * STAGE_BYTES;
        uint32_t b = sB + st * STAGE_BYTES;
        int k0 = c * 32;
        #pragma unroll
        for (int it = 0; it < 2; it++) {
            int id = tid + it * 256;
            int r = id >> 2, s = id & 3;
            uint32_t off = (uint32_t)(r * PITCH + s * 8) * 2;
            cpasync16(a + off, X + (size_t)(bm + r) * K + k0 + s * 8);
            cpasync16(b + off, W + (size_t)(bn + r) * K + k0 + s * 8);
        }
    };

    #pragma unroll
    for (int c = 0; c < NSTAGE - 1; c++) { stage_load(c, c); CP_COMMIT(); }

    for (int c = 0; c < NC; c++) {
        int st = c & (NSTAGE - 1);
        CP_WAIT2();
        __syncthreads();
        if (c + NSTAGE - 1 < NC) stage_load((c + NSTAGE - 1) & (NSTAGE - 1), c + NSTAGE - 1);
        CP_COMMIT();

        uint32_t aBase = sA + st * STAGE_BYTES;
        uint32_t bBase = sB + st * STAGE_BYTES;
        #pragma unroll
        for (int kk = 0; kk < 2; kk++) {
            uint32_t af[4][4], bf[4][2];
            #pragma unroll
            for (int mi = 0; mi < 4; mi++) {
                int row = wm * 64 + mi * 16 + (lane & 15);
                ldsm4(af[mi], aBase + (uint32_t)(row * PITCH + kk * 16 + (lane >> 4) * 8) * 2);
            }
            #pragma unroll
            for (int ni = 0; ni < 4; ni++) {
                int row = wn * 32 + ni * 8 + (lane & 7);
                ldsm2(bf[ni], bBase + (uint32_t)(row * PITCH + kk * 16 + ((lane >> 3) & 1) * 8) * 2);
            }
            #pragma unroll
            for (int mi = 0; mi < 4; mi++)
                #pragma unroll
                for (int ni = 0; ni < 4; ni++)
                    mma16816(acc[mi][ni], af[mi], bf[ni]);
        }
    }
    CP_WAIT0();

    #pragma unroll
    for (int mi = 0; mi < 4; mi++)
        #pragma unroll
        for (int ni = 0; ni < 4; ni++) {
            int gn = bn + wn * 32 + ni * 8 + (lane & 3) * 2;
            #pragma unroll
            for (int h = 0; h < 2; h++) {
                int gm = bm + wm * 64 + mi * 16 + (lane >> 2) + h * 8;
                *(__nv_bfloat162*)(outp + (size_t)gm * out_stride + gn) =
                    __floats2bfloat162_rn(acc[mi][ni][h * 2], acc[mi][ni][h * 2 + 1]);
            }
        }
}

// ================= fp8 GEMM =================
enum { QEPI_SIG = 0, QEPI_BF16 = 1, QEPI_FP8 = 2, QEPI_GATE = 3, QEPI_RESID = 4 };

// C[m,n] = inv_s * sum_k X[m,k]*W[n,k] + bias; X,W fp8 e4m3, rows of Kb bytes
template<int EPI>
__global__ void __launch_bounds__(256, 2) qgemm_k(
    const uint8_t* __restrict__ X, const uint8_t* __restrict__ W,
    const float* __restrict__ bias, void* __restrict__ outp, int ostride,
    const __nv_bfloat16* __restrict__ gate, const float* __restrict__ resid,
    int Kb, float inv_s, float s_out)
{
    extern __shared__ char smem[];
    uint32_t sA = smem_u32(smem);
    uint32_t sB = sA + NSTAGE * QSTAGE;
    int tid = threadIdx.x, warp = tid >> 5, lane = tid & 31;
    int wm = warp >> 2, wn = warp & 3;           // 2x4 warp grid, warp tile 64x32
    int bm = blockIdx.y * BM, bn = blockIdx.x * BN;
    int NC = Kb / 64;

    float acc[4][4][4];
    #pragma unroll
    for (int mi = 0; mi < 4; mi++)
        #pragma unroll
        for (int ni = 0; ni < 4; ni++)
            #pragma unroll
            for (int e = 0; e < 4; e++) acc[mi][ni][e] = 0.f;

    auto stage_load = [&](int st, int c) {
        uint32_t a = sA + st * QSTAGE;
        uint32_t b = sB + st * QSTAGE;
        int k0 = c * 64;
        #pragma unroll
        for (int it = 0; it < 2; it++) {
            int id = tid + it * 256;
            int r = id >> 2, s = id & 3;
            uint32_t off = (uint32_t)(r * QPITCH + s * 16);
            cpasync16(a + off, X + (size_t)(bm + r) * Kb + k0 + s * 16);
            cpasync16(b + off, W + (size_t)(bn + r) * Kb + k0 + s * 16);
        }
    };

    #pragma unroll
    for (int c = 0; c < NSTAGE - 1; c++) { stage_load(c, c); CP_COMMIT(); }

    for (int c = 0; c < NC; c++) {
        int st = c & (NSTAGE - 1);
        CP_WAIT2();
        __syncthreads();
        if (c + NSTAGE - 1 < NC) stage_load((c + NSTAGE - 1) & (NSTAGE - 1), c + NSTAGE - 1);
        CP_COMMIT();

        uint32_t aBase = sA + st * QSTAGE;
        uint32_t bBase = sB + st * QSTAGE;
        #pragma unroll
        for (int kk = 0; kk < 2; kk++) {       // two k32 halves of the 64B chunk
            uint32_t af[4][4], bf[4][2];
            #pragma unroll
            for (int mi = 0; mi < 4; mi++) {
                int row = wm * 64 + mi * 16 + (lane & 15);
                ldsm4(af[mi], aBase + (uint32_t)(row * QPITCH + kk * 32 + (lane >> 4) * 16));
            }
            #pragma unroll
            for (int ni = 0; ni < 4; ni++) {
                int row = wn * 32 + ni * 8 + (lane & 7);
                ldsm2(bf[ni], bBase + (uint32_t)(row * QPITCH + kk * 32 + ((lane >> 3) & 1) * 16));
            }
            #pragma unroll
            for (int mi = 0; mi < 4; mi++)
                #pragma unroll
                for (int ni = 0; ni < 4; ni++)
                    qmma16832(acc[mi][ni], af[mi], bf[ni]);
        }
    }
    CP_WAIT0();

    // -------- epilogue --------
    #pragma unroll
    for (int mi = 0; mi < 4; mi++) {
        #pragma unroll
        for (int ni = 0; ni < 4; ni++) {
            int gn = bn + wn * 32 + ni * 8 + (lane & 3) * 2;
            float b0 = 0.f, b1 = 0.f;
            if (bias) { b0 = bias[gn]; b1 = bias[gn + 1]; }
            #pragma unroll
            for (int h = 0; h < 2; h++) {
                int gm = bm + wm * 64 + mi * 16 + (lane >> 2) + h * 8;
                float v0 = acc[mi][ni][h * 2 + 0] * inv_s + b0;
                float v1 = acc[mi][ni][h * 2 + 1] * inv_s + b1;
                if (EPI == QEPI_SIG) {
                    v0 = 1.f / (1.f + __expf(-v0));
                    v1 = 1.f / (1.f + __expf(-v1));
                }
                if (EPI == QEPI_GATE) {
                    __nv_bfloat162 g2 = *(const __nv_bfloat162*)(gate + (size_t)gm * DI + gn);
                    v0 *= __bfloat162float(g2.x);
                    v1 *= __bfloat162float(g2.y);
                }
                if (EPI == QEPI_SIG || EPI == QEPI_BF16) {
                    __nv_bfloat16* op = (__nv_bfloat16*)outp + (size_t)gm * ostride + gn;
                    *(__nv_bfloat162*)op = __floats2bfloat162_rn(v0, v1);
                } else if (EPI == QEPI_FP8 || EPI == QEPI_GATE) {
                    uint8_t* op = (uint8_t*)outp + (size_t)gm * ostride + gn;
                    *(uint16_t*)op = f2fp8x2(v0 * s_out, v1 * s_out);
                } else {  // QEPI_RESID
                    const float* rp = resid + (size_t)gm * ostride + gn;
                    float* op = (float*)outp + (size_t)gm * ostride + gn;
                    float2 r2 = *(const float2*)rp;
                    float2 o2; o2.x = v0 + r2.x; o2.y = v1 + r2.y;
                    *(float2*)op = o2;
                }
            }
        }
    }
}

// ---------------- small kernels ----------------
__global__ void f2bf_k(const float* __restrict__ s, __nv_bfloat16* __restrict__ d, int n) {
    int i = blockIdx.x * 256 + threadIdx.x;
    if (i < n) d[i] = __float2bfloat16(s[i]);
}
__global__ void f2fp8_k(const float* __restrict__ s, uint8_t* __restrict__ d, float sc, int n) {
    int i = blockIdx.x * 256 + threadIdx.x;
    if (i < n) d[i] = f2fp8(s[i] * sc);
}
__global__ void bf2fp8_k(const __nv_bfloat16* __restrict__ s, uint8_t* __restrict__ d, float sc, int n) {
    int i = blockIdx.x * 256 + threadIdx.x;
    if (i < n) d[i] = f2fp8(__bfloat162float(s[i]) * sc);
}

__global__ void rmsnorm_k(const float* __restrict__ x, const float* __restrict__ w) {
    int row = blockIdx.x;
    int tid = threadIdx.x;
    const float* xr = x + (size_t)row * D_MODEL;
    float s = 0.f;
    for (int i = tid; i < D_MODEL; i += 256) { float v = xr[i]; s += v * v; }
    __shared__ float red[256];
    red[tid] = s; __syncthreads();
    for (int o = 128; o > 0; o >>= 1) {
        if (tid < o) red[tid] += red[tid + o];
        __syncthreads();
    }
    float scale = rsqrtf(red[0] / (float)D_MODEL + 1e-6f) * S_XN;
    for (int i = tid; i < D_MODEL; i += 256)
        g_xn8[(size_t)row * D_MODEL + i] = f2fp8(xr[i] * w[i] * scale);
}

// 32x32 tiled transpose: g_pwT[c][o] = pw_w[o][c], fp32 -> bf16
__global__ void transpose_pw_k(const float* __restrict__ src) {
    __shared__ float t[32][33];
    int bx = blockIdx.x * 32, by = blockIdx.y * 32;
    int tx = threadIdx.x, ty = threadIdx.y;
    #pragma unroll
    for (int i = 0; i < 32; i += 8)
        t[ty + i][tx] = src[(size_t)(by + ty + i) * DI + bx + tx];
    __syncthreads();
    #pragma unroll
    for (int i = 0; i < 32; i += 8)
        g_pwT[(size_t)(bx + ty + i) * DI + by + tx] = __float2bfloat16(t[tx][ty + i]);
}

// fused depthwise convs: ca (4-tap, bf16) and cb8 = fp8(silu(9-tap) * S_CB)
#define CL 128
#define CD 64
__global__ void __launch_bounds__(256) conv_fused_k(
    const float* __restrict__ ka, const float* __restrict__ ba,
    const float* __restrict__ ks, const float* __restrict__ bs)
{
    __shared__ __nv_bfloat16 sv[CL + 8][CD];
    int d0 = blockIdx.x * CD;
    int l0 = blockIdx.y * CL;
    int b  = blockIdx.z;
    const __nv_bfloat16* vb = g_val + (size_t)b * L_SEQ * DI;
    int tid = threadIdx.x;
    for (int i = tid; i < (CL + 8) * 8; i += 256) {
        int r = i >> 3, s = i & 7;
        int l = l0 - 4 + r;
        uint4 v = make_uint4(0, 0, 0, 0);
        if (l >= 0 && l < L_SEQ)
            v = *(const uint4*)(vb + (size_t)l * DI + d0 + s * 8);
        *(uint4*)(&sv[r][s * 8]) = v;
    }
    __syncthreads();
    int d = tid & (CD - 1);
    int lw = tid >> 6;
    float wa[4], w9[9];
    #pragma unroll
    for (int j = 0; j < 4; j++) wa[j] = ka[(d0 + d) * 4 + j];
    #pragma unroll
    for (int j = 0; j < 9; j++) w9[j] = ks[(d0 + d) * 9 + j];
    float bav = ba[d0 + d], bsv = bs[d0 + d];
    for (int li = 0; li < CL / 4; li++) {
        int l = lw * (CL / 4) + li;
        float aa = bav, ab = bsv;
        #pragma unroll
        for (int j = 0; j < 4; j++) aa += __bfloat162float(sv[l + 3 + j][d]) * wa[j];
        #pragma unroll
        for (int j = 0; j < 9; j++) ab += __bfloat162float(sv[l + j][d]) * w9[j];
        size_t o = ((size_t)b * L_SEQ + l0 + l) * DI + d0 + d;
        g_ca[o] = __float2bfloat16(aa);
        float sg = 1.f / (1.f + __expf(-ab));
        g_cb8[o] = f2fp8(ab * sg * S_CB);
    }
}

// T[s][n] = sum_d Bm[s,d] * ha_w[n,d]
__global__ void compute_T_k(const float* __restrict__ Bm, const float* __restrict__ haw) {
    int n = blockIdx.x;
    int tid = threadIdx.x;
    float acc[DS];
    #pragma unroll
    for (int s = 0; s < DS; s++) acc[s] = 0.f;
    for (int d = tid; d < DI; d += 128) {
        float h = haw[(size_t)n * DI + d];
        #pragma unroll
        for (int s = 0; s < DS; s++) acc[s] += h * Bm[s * DI + d];
    }
    __shared__ float red[DS * 128];
    #pragma unroll
    for (int s = 0; s < DS; s++) red[s * 128 + tid] = acc[s];
    __syncthreads();
    if (tid < DS) {
        float t = 0.f;
        for (int i = 0; i < 128; i++) t += red[tid * 128 + i];
        g_T[tid * DH + n] = t;
    }
}

// a1[m, 0:16] = S_YC * sum_d ca[m,d] * A[d,s]; zero bytes 16..63. One warp per token.
__global__ void __launch_bounds__(256) a1_k(const float* __restrict__ A) {
    int warp = threadIdx.x >> 5, lane = threadIdx.x & 31;
    size_t m = (size_t)blockIdx.x * 8 + warp;
    const __nv_bfloat16* car = g_ca + m * DI;
    float acc[16];
    #pragma unroll
    for (int s = 0; s < 16; s++) acc[s] = 0.f;
    for (int d = lane; d < DI; d += 32) {
        float c = __bfloat162float(car[d]);
        const float4* Ar = (const float4*)(A + (size_t)d * 16);
        float4 a0 = Ar[0], a1v = Ar[1], a2 = Ar[2], a3 = Ar[3];
        acc[0]  += c * a0.x;  acc[1]  += c * a0.y;  acc[2]  += c * a0.z;  acc[3]  += c * a0.w;
        acc[4]  += c * a1v.x; acc[5]  += c * a1v.y; acc[6]  += c * a1v.z; acc[7]  += c * a1v.w;
        acc[8]  += c * a2.x;  acc[9]  += c * a2.y;  acc[10] += c * a2.z;  acc[11] += c * a2.w;
        acc[12] += c * a3.x;  acc[13] += c * a3.y;  acc[14] += c * a3.z;  acc[15] += c * a3.w;
    }
    #pragma unroll
    for (int s = 0; s < 16; s++)
        #pragma unroll
        for (int o = 16; o > 0; o >>= 1)
            acc[s] += __shfl_xor_sync(0xFFFFFFFFu, acc[s], o);
    if (lane == 0) {
        uint32_t w[4];
        #pragma unroll
        for (int h = 0; h < 4; h++) {
            uint32_t lo = f2fp8x2(acc[4 * h] * S_YC, acc[4 * h + 1] * S_YC);
            uint32_t hi = f2fp8x2(acc[4 * h + 2] * S_YC, acc[4 * h + 3] * S_YC);
            w[h] = lo | (hi << 16);
        }
        uint4* dst = (uint4*)(g_yc8 + m * YK8);
        dst[0] = make_uint4(w[0], w[1], w[2], w[3]);
        dst[1] = make_uint4(0, 0, 0, 0);
        dst[2] = make_uint4(0, 0, 0, 0);
        dst[3] = make_uint4(0, 0, 0, 0);
    }
}

// wf8[n][s] = fp8(S_W * sum_t T[s,t]*fuse_w[n,t]); bytes 16..63 zero
__global__ void wf_u_k(const float* __restrict__ fw) {
    int n = blockIdx.x;
    int tid = threadIdx.x;   // 128
    float acc[DS];
    #pragma unroll
    for (int s = 0; s < DS; s++) acc[s] = 0.f;
    for (int t = tid; t < DH; t += 128) {
        float f = fw[(size_t)n * DI + t];
        #pragma unroll
        for (int s = 0; s < DS; s++) acc[s] += f * g_T[s * DH + t];
    }
    __shared__ float red[DS * 128];
    #pragma unroll
    for (int s = 0; s < DS; s++) red[s * 128 + tid] = acc[s];
    __syncthreads();
    if (tid < DS) {
        float t = 0.f;
        for (int i = 0; i < 128; i++) t += red[tid * 128 + i];
        g_wf8[(size_t)n * YK8 + tid] = f2fp8(t * S_W);
    } else if (tid < 64) {
        g_wf8[(size_t)n * YK8 + tid] = 0;
    }
}

// wf8[n][64+j] = fp8(S_W * fuse_w[n][1024+j])
__global__ void wf_copy_k(const float* __restrict__ fw) {
    int idx = blockIdx.x * 256 + threadIdx.x;      // DI * DH
    int n = idx >> 10, j = idx & 1023;
    g_wf8[(size_t)n * YK8 + 64 + j] = f2fp8(fw[(size_t)n * DI + DH + j] * S_W);
}

// biasy[n] = fuse_b[n] + sum_{t<1024} fuse_w[n,t] * ha_b[t]
__global__ void bias_y_k(const float* __restrict__ fw, const float* __restrict__ hab,
                         const float* __restrict__ fb) {
    int n = blockIdx.x;
    int tid = threadIdx.x;
    float a = 0.f;
    for (int t = tid; t < DH; t += 256) a += fw[(size_t)n * DI + t] * hab[t];
    __shared__ float red[256];
    red[tid] = a; __syncthreads();
    for (int o = 128; o > 0; o >>= 1) {
        if (tid < o) red[tid] += red[tid + o];
        __syncthreads();
    }
    if (tid == 0) g_biasy[n] = red[0] + fb[n];
}

// bias_b[n] = hb_b[n] + sum_d hb_w[n,d]*pw_b[d]
__global__ void bias_b_k(const float* __restrict__ hbw, const float* __restrict__ pwb,
                         const float* __restrict__ hbb) {
    int n = blockIdx.x;
    int tid = threadIdx.x;
    float a = 0.f;
    for (int d = tid; d < DI; d += 256) a += hbw[(size_t)n * DI + d] * pwb[d];
    __shared__ float red[256];
    red[tid] = a; __syncthreads();
    for (int o = 128; o > 0; o >>= 1) {
        if (tid < o) red[tid] += red[tid + o];
        __syncthreads();
    }
    if (tid == 0) g_biasb[n] = red[0] + hbb[n];
}

// ---------------- launch ----------------
static void* sym_addr(const void* s) {
    void* p = nullptr;
    cudaGetSymbolAddress(&p, s);
    return p;
}

extern "C" void kernel_launch(void* const* d_in, const int* in_sizes, int n_in,
                              void* d_out, int out_size) {
    const float* x      = (const float*)d_in[0];
    const float* norm_w = (const float*)d_in[1];
    const float* in_w   = (const float*)d_in[2];
    const float* in_b   = (const float*)d_in[3];
    const float* dwa_k  = (const float*)d_in[4];
    const float* dwa_b  = (const float*)d_in[5];
    const float* A      = (const float*)d_in[6];
    const float* Bm     = (const float*)d_in[7];
    const float* sym_k  = (const float*)d_in[8];
    const float* sym_b  = (const float*)d_in[9];
    const float* pw_w   = (const float*)d_in[10];
    const float* pw_b   = (const float*)d_in[11];
    const float* ha_w   = (const float*)d_in[12];
    const float* ha_b   = (const float*)d_in[13];
    const float* hb_w   = (const float*)d_in[14];
    const float* hb_b   = (const float*)d_in[15];
    const float* fuse_w = (const float*)d_in[16];
    const float* fuse_b = (const float*)d_in[17];
    const float* out_w  = (const float*)d_in[18];
    const float* out_b  = (const float*)d_in[19];

    uint8_t*       p_xn8   = (uint8_t*)sym_addr(g_xn8);
    __nv_bfloat16* p_gate  = (__nv_bfloat16*)sym_addr(g_gate);
    __nv_bfloat16* p_val   = (__nv_bfloat16*)sym_addr(g_val);
    __nv_bfloat16* p_ca    = (__nv_bfloat16*)sym_addr(g_ca);
    uint8_t*       p_cb8   = (uint8_t*)sym_addr(g_cb8);
    uint8_t*       p_yc8   = (uint8_t*)sym_addr(g_yc8);
    uint8_t*       p_f8    = (uint8_t*)sym_addr(g_f8);
    uint8_t*       p_inw8  = (uint8_t*)sym_addr(g_inw8);
    uint8_t*       p_outw8 = (uint8_t*)sym_addr(g_outw8);
    uint8_t*       p_Wb8   = (uint8_t*)sym_addr(g_Wb8);
    uint8_t*       p_wf8   = (uint8_t*)sym_addr(g_wf8);
    __nv_bfloat16* p_hbw   = (__nv_bfloat16*)sym_addr(g_hbw);
    __nv_bfloat16* p_pwT   = (__nv_bfloat16*)sym_addr(g_pwT);
    __nv_bfloat16* p_Wb    = (__nv_bfloat16*)sym_addr(g_Wb);
    float*         p_biasb = (float*)sym_addr(g_biasb);
    float*         p_biasy = (float*)sym_addr(g_biasy);

    cudaFuncSetAttribute(mma_gemm_k,        cudaFuncAttributeMaxDynamicSharedMemorySize, SMEM_TOTAL);
    cudaFuncSetAttribute(qgemm_k<QEPI_SIG>,   cudaFuncAttributeMaxDynamicSharedMemorySize, QSMEM_TOTAL);
    cudaFuncSetAttribute(qgemm_k<QEPI_BF16>,  cudaFuncAttributeMaxDynamicSharedMemorySize, QSMEM_TOTAL);
    cudaFuncSetAttribute(qgemm_k<QEPI_FP8>,   cudaFuncAttributeMaxDynamicSharedMemorySize, QSMEM_TOTAL);
    cudaFuncSetAttribute(qgemm_k<QEPI_GATE>,  cudaFuncAttributeMaxDynamicSharedMemorySize, QSMEM_TOTAL);
    cudaFuncSetAttribute(qgemm_k<QEPI_RESID>, cudaFuncAttributeMaxDynamicSharedMemorySize, QSMEM_TOTAL);

    auto cgrid = [](int n) { return (n + 255) / 256; };

    const float INV_IN  = 1.f / (S_XN * S_W);     // gate/val
    const float INV_BH  = 1.f / (S_CB * S_W);     // b_h
    const float INV_Y   = 1.f / (S_YC * S_W);     // y
    const float INV_OUT = 1.f / (S_F * S_W);      // out

    // launch order: #4 (1-based) = val GEMM -> profiled by ncu -s/-c
    rmsnorm_k<<<M_TOK, 256>>>(x, norm_w);                                        // 1
    f2fp8_k<<<cgrid(2 * DI * D_MODEL), 256>>>(in_w, p_inw8, S_W, 2 * DI * D_MODEL); // 2

    dim3 gdIn(DI / BN, M_TOK / BM);
    qgemm_k<QEPI_SIG><<<gdIn, 256, QSMEM_TOTAL>>>(p_xn8, p_inw8, in_b, p_gate, DI,   // 3
                                                  nullptr, nullptr, D_MODEL, INV_IN, 0.f);
    qgemm_k<QEPI_BF16><<<gdIn, 256, QSMEM_TOTAL>>>(p_xn8, p_inw8 + (size_t)DI * D_MODEL, // 4
                                                   in_b + DI, p_val, DI,
                                                   nullptr, nullptr, D_MODEL, INV_IN, 0.f);

    f2bf_k<<<cgrid(DH * DI), 256>>>(hb_w, p_hbw, DH * DI);
    transpose_pw_k<<<dim3(DI / 32, DI / 32), dim3(32, 8)>>>(pw_w);

    conv_fused_k<<<dim3(DI / CD, L_SEQ / CL, 4), 256>>>(dwa_k, dwa_b, sym_k, sym_b);

    // folded-weight precomputes
    compute_T_k<<<DH, 128>>>(Bm, ha_w);
    mma_gemm_k<<<dim3(DI / BN, DH / BM), 256, SMEM_TOTAL>>>(p_hbw, p_pwT, p_Wb, DI, DI);
    bf2fp8_k<<<cgrid(DH * DI), 256>>>(p_Wb, p_Wb8, S_W, DH * DI);
    bias_b_k<<<DH, 256>>>(hb_w, pw_b, hb_b);
    wf_u_k<<<DI, 128>>>(fuse_w);
    wf_copy_k<<<cgrid(DI * DH), 256>>>(fuse_w);
    bias_y_k<<<DI, 256>>>(fuse_w, ha_b, fuse_b);
    f2fp8_k<<<cgrid(D_MODEL * DI), 256>>>(out_w, p_outw8, S_W, D_MODEL * DI);

    // a-branch through rank-16 bottleneck
    a1_k<<<M_TOK / 8, 256>>>(A);

    // b-branch: b_h = cb @ Wb + biasb  (fp8 out into yc bytes 64..1087)
    qgemm_k<QEPI_FP8><<<dim3(DH / BN, M_TOK / BM), 256, QSMEM_TOTAL>>>(
        p_cb8, p_Wb8, p_biasb, p_yc8 + 64, YK8, nullptr, nullptr, DI, INV_BH, S_YC);

    // fused y GEMM: y = [a1|b_h] @ wf^T + biasy, gated (K=1088 fp8)
    qgemm_k<QEPI_GATE><<<dim3(DI / BN, M_TOK / BM), 256, QSMEM_TOTAL>>>(
        p_yc8, p_wf8, p_biasy, p_f8, DI, p_gate, nullptr, YK8, INV_Y, S_F);

    // out projection (+ residual), fp32 output
    qgemm_k<QEPI_RESID><<<dim3(D_MODEL / BN, M_TOK / BM), 256, QSMEM_TOTAL>>>(
        p_f8, p_outw8, out_b, d_out, D_MODEL, nullptr, x, DI, INV_OUT, 0.f);
}